// round 7
// baseline (speedup 1.0000x reference)
#include <cuda_runtime.h>
#include <cstdint>

// ---------------------------------------------------------------------------
// Problem constants
// ---------------------------------------------------------------------------
#define Bb   32
#define Nn   512
#define NT   24
#define Hh   8
#define DH   48
#define Ee   384          // H*DH
#define INd  768          // C*NT
#define OUTd 768
#define E3   1152         // 3*E
#define Mrows (Bb*Nn)     // 16384

// ---------------------------------------------------------------------------
// Scratch (device globals)
// ---------------------------------------------------------------------------
__device__ float g_qkv_t[(size_t)Mrows * E3];
__device__ float g_qkv_s[(size_t)Mrows * E3];
__device__ float g_xt[(size_t)Mrows * Ee];
__device__ float g_xs[(size_t)Mrows * Ee];
__device__ float g_alpha_in[Bb * 2 * Ee];
__device__ float g_gate0[Bb * Ee];
__device__ float g_gate1[Bb * Ee];

// ---------------------------------------------------------------------------
// tf32 / cp.async helpers
// ---------------------------------------------------------------------------
__device__ __forceinline__ uint32_t f2tf32(float f) {
    uint32_t o;
    asm("cvt.rna.tf32.f32 %0, %1;" : "=r"(o) : "f"(f));
    return o;
}

__device__ __forceinline__ void mma_tf32(float c[4],
                                         uint32_t a0, uint32_t a1,
                                         uint32_t a2, uint32_t a3,
                                         uint32_t b0, uint32_t b1) {
    asm volatile(
        "mma.sync.aligned.m16n8k8.row.col.f32.tf32.tf32.f32 "
        "{%0,%1,%2,%3}, {%4,%5,%6,%7}, {%8,%9}, {%0,%1,%2,%3};\n"
        : "+f"(c[0]), "+f"(c[1]), "+f"(c[2]), "+f"(c[3])
        : "r"(a0), "r"(a1), "r"(a2), "r"(a3), "r"(b0), "r"(b1));
}

__device__ __forceinline__ void cp_async16(void* smem_dst, const void* gmem_src) {
    uint32_t d = (uint32_t)__cvta_generic_to_shared(smem_dst);
    asm volatile("cp.async.cg.shared.global [%0], [%1], 16;\n"
                 :: "r"(d), "l"(gmem_src));
}
__device__ __forceinline__ void cp_async_commit() {
    asm volatile("cp.async.commit_group;\n");
}
__device__ __forceinline__ void cp_async_wait_all() {
    asm volatile("cp.async.wait_group 0;\n");
}

// ---------------------------------------------------------------------------
// tf32 mma.sync GEMM, 128x128 tile, BK=32, 256 threads, double buffered,
// in-place tf32 conversion after cp.async lands.
//
// MODE 0 (dual-N QKV): one A, two W/bias/C halves selected by blockIdx.x:
//         bx in [0,9)  -> C0 = A @ W0 + bias0   (cols bx*128)
//         bx in [9,18) -> C1 = A @ W1 + bias1   (cols (bx-9)*128)
// MODE 1 (fused out): C = (A0*g0[b]) @ W0 + (A1*g1[b]) @ W1 + bias0 + bias1
//         gate applied to B rows during the conversion pass.
// ---------------------------------------------------------------------------
template <int MODE>
__global__ __launch_bounds__(256, 2)
void mma_gemm(const float* __restrict__ A0, const float* __restrict__ A1,
              const float* __restrict__ W0, const float* __restrict__ W1,
              const float* __restrict__ g0p, const float* __restrict__ g1p,
              const float* __restrict__ bias0, const float* __restrict__ bias1,
              float* __restrict__ C0, float* __restrict__ C1,
              int Kd, int Nd)
{
    extern __shared__ float smem[];
    float (*As)[128][36] = reinterpret_cast<float(*)[128][36]>(smem);
    float (*Bs)[32][132] = reinterpret_cast<float(*)[32][132]>(smem + 2 * 128 * 36);

    const int tid  = threadIdx.x;
    const int lane = tid & 31;
    const int warp = tid >> 5;
    const int g    = lane >> 2;
    const int tig  = lane & 3;
    const int warpM = (warp & 1) * 64;
    const int warpN = (warp >> 1) * 32;

    const int rowBase = blockIdx.y * 128;
    const int bIdx = rowBase >> 9;

    int colBase, half = 0;
    const float* Wsel;
    const float* biasSel;
    float* Csel;
    if (MODE == 0) {
        half = (blockIdx.x >= 9);
        colBase = (blockIdx.x - half * 9) * 128;
        Wsel = half ? W1 : W0;
        biasSel = half ? bias1 : bias0;
        Csel = half ? C1 : C0;
    } else {
        colBase = blockIdx.x * 128;
        Wsel = nullptr; biasSel = nullptr; Csel = C0;
    }

    const int perPass = Kd >> 5;
    const int nChunks = (MODE == 1) ? 2 * perPass : perPass;

    auto issueLoad = [&](int c, int buf) {
        int pass = (MODE == 1) ? (c / perPass) : 0;
        int k0 = ((MODE == 1) ? (c - pass * perPass) : c) << 5;
        const float* A = (MODE == 1 && pass) ? A1 : A0;
        const float* W = (MODE == 0) ? Wsel : (pass ? W1 : W0);
        // A tile: 128 x 32 floats = 1024 float4
#pragma unroll
        for (int i = 0; i < 4; ++i) {
            int idx = i * 256 + tid;
            int r = idx >> 3, c4 = idx & 7;
            cp_async16(&As[buf][r][c4 * 4],
                       &A[(size_t)(rowBase + r) * Kd + k0 + c4 * 4]);
        }
        // B tile: 32 x 128 floats = 1024 float4 (W is [K][Nd] row-major)
#pragma unroll
        for (int i = 0; i < 4; ++i) {
            int idx = i * 256 + tid;
            int r = idx >> 5, c4 = idx & 31;
            cp_async16(&Bs[buf][r][c4 * 4],
                       &W[(size_t)(k0 + r) * Nd + colBase + c4 * 4]);
        }
        cp_async_commit();
    };

    float acc[4][4][4];
#pragma unroll
    for (int i = 0; i < 4; ++i)
#pragma unroll
        for (int j = 0; j < 4; ++j)
#pragma unroll
            for (int r = 0; r < 4; ++r) acc[i][j][r] = 0.0f;

    issueLoad(0, 0);

    for (int c = 0; c < nChunks; ++c) {
        const int buf = c & 1;
        cp_async_wait_all();
        __syncthreads();
        if (c + 1 < nChunks) issueLoad(c + 1, buf ^ 1);

        // ---- in-place tf32 conversion (plus gate on B for MODE 1) ----
        const float* gate = nullptr;
        if (MODE == 1) {
            int pass = c / perPass;
            int kBase = (c - pass * perPass) << 5;
            gate = (pass ? g1p : g0p) + bIdx * Ee + kBase;
        }
#pragma unroll
        for (int q = 0; q < 4; ++q) {
            int idx = tid * 4 + q;
            int r = idx >> 3, c4 = idx & 7;
            float4* p = reinterpret_cast<float4*>(&As[buf][r][c4 * 4]);
            float4 v = *p;
            uint4 t;
            t.x = f2tf32(v.x); t.y = f2tf32(v.y);
            t.z = f2tf32(v.z); t.w = f2tf32(v.w);
            *reinterpret_cast<uint4*>(p) = t;
        }
#pragma unroll
        for (int q = 0; q < 4; ++q) {
            int idx = tid * 4 + q;
            int r = idx >> 5, c4 = idx & 31;
            float4* p = reinterpret_cast<float4*>(&Bs[buf][r][c4 * 4]);
            float4 v = *p;
            if (MODE == 1) {
                float gv = gate[r];
                v.x *= gv; v.y *= gv; v.z *= gv; v.w *= gv;
            }
            uint4 t;
            t.x = f2tf32(v.x); t.y = f2tf32(v.y);
            t.z = f2tf32(v.z); t.w = f2tf32(v.w);
            *reinterpret_cast<uint4*>(p) = t;
        }
        __syncthreads();

        // ---- compute: 4 kk-slices of 8 ----
#pragma unroll
        for (int kk = 0; kk < 32; kk += 8) {
            uint32_t af[4][4];
#pragma unroll
            for (int i = 0; i < 4; ++i) {
                int m0 = warpM + 16 * i;
                af[i][0] = __float_as_uint(As[buf][m0 + g][kk + tig]);
                af[i][1] = __float_as_uint(As[buf][m0 + g + 8][kk + tig]);
                af[i][2] = __float_as_uint(As[buf][m0 + g][kk + tig + 4]);
                af[i][3] = __float_as_uint(As[buf][m0 + g + 8][kk + tig + 4]);
            }
            uint32_t bf[4][2];
#pragma unroll
            for (int j = 0; j < 4; ++j) {
                int n0 = warpN + 8 * j;
                bf[j][0] = __float_as_uint(Bs[buf][kk + tig][n0 + g]);
                bf[j][1] = __float_as_uint(Bs[buf][kk + tig + 4][n0 + g]);
            }
#pragma unroll
            for (int i = 0; i < 4; ++i)
#pragma unroll
                for (int j = 0; j < 4; ++j)
                    mma_tf32(acc[i][j], af[i][0], af[i][1], af[i][2],
                             af[i][3], bf[j][0], bf[j][1]);
        }
    }
    __syncthreads();

    // ---- epilogue ----
#pragma unroll
    for (int i = 0; i < 4; ++i) {
#pragma unroll
        for (int j = 0; j < 4; ++j) {
            int col = colBase + warpN + 8 * j + 2 * tig;
            float bsum0, bsum1;
            if (MODE == 1) {
                bsum0 = bias0[col] + bias1[col];
                bsum1 = bias0[col + 1] + bias1[col + 1];
            } else {
                bsum0 = biasSel[col];
                bsum1 = biasSel[col + 1];
            }
            int row0 = rowBase + warpM + 16 * i + g;
            float* Cw = (MODE == 0) ? Csel : C0;
            float2 o0 = make_float2(acc[i][j][0] + bsum0, acc[i][j][1] + bsum1);
            *reinterpret_cast<float2*>(&Cw[(size_t)row0 * Nd + col]) = o0;
            float2 o1 = make_float2(acc[i][j][2] + bsum0, acc[i][j][3] + bsum1);
            *reinterpret_cast<float2*>(&Cw[(size_t)(row0 + 8) * Nd + col]) = o1;
        }
    }
}

#define GEMM_SMEM (2 * (128 * 36 + 32 * 132) * 4)

// ---------------------------------------------------------------------------
// Flash temporal attention (unchanged, passing)
// ---------------------------------------------------------------------------
__global__ __launch_bounds__(128)
void flash_tattn(const float* __restrict__ qkv, float* __restrict__ xt)
{
    __shared__ float QP[64][68];
    __shared__ float Ks[64][52];
    __shared__ float Vt[48][68];

    const int b = blockIdx.z, h = blockIdx.y;
    const int q0 = blockIdx.x * 64;
    const int tid = threadIdx.x;
    const int warp = tid >> 5, lane = tid & 31;
    const int g = lane >> 2, tig = lane & 3;
    const int m0 = warp * 16;
    const float scale = 0.14433756729740643f;

    const float* base = qkv + (size_t)(b * Nn) * E3 + h * DH;

    for (int i = tid; i < 64 * 12; i += 128) {
        int r = i / 12, f = i % 12;
        float4 v = *reinterpret_cast<const float4*>(
            &base[(size_t)(q0 + r) * E3 + 4 * f]);
        v.x *= scale; v.y *= scale; v.z *= scale; v.w *= scale;
        *reinterpret_cast<float4*>(&QP[r][4 * f]) = v;
    }
    __syncthreads();

    uint32_t qf[6][4];
#pragma unroll
    for (int kc = 0; kc < 6; ++kc) {
        qf[kc][0] = f2tf32(QP[m0 + g][8 * kc + tig]);
        qf[kc][1] = f2tf32(QP[m0 + g + 8][8 * kc + tig]);
        qf[kc][2] = f2tf32(QP[m0 + g][8 * kc + tig + 4]);
        qf[kc][3] = f2tf32(QP[m0 + g + 8][8 * kc + tig + 4]);
    }
    __syncthreads();

    float of[6][4];
#pragma unroll
    for (int nb = 0; nb < 6; ++nb)
#pragma unroll
        for (int r = 0; r < 4; ++r) of[nb][r] = 0.0f;
    float mr0 = -1e30f, mr1 = -1e30f, l0 = 0.0f, l1 = 0.0f;

    for (int c0 = 0; c0 < Nn; c0 += 64) {
        for (int i = tid; i < 64 * 12; i += 128) {
            int r = i / 12, f = i % 12;
            const float* src = &base[(size_t)(c0 + r) * E3 + 4 * f];
            float4 kv = *reinterpret_cast<const float4*>(src + Ee);
            *reinterpret_cast<float4*>(&Ks[r][4 * f]) = kv;
            float4 vv = *reinterpret_cast<const float4*>(src + 2 * Ee);
            Vt[4 * f + 0][r] = vv.x;
            Vt[4 * f + 1][r] = vv.y;
            Vt[4 * f + 2][r] = vv.z;
            Vt[4 * f + 3][r] = vv.w;
        }
        __syncthreads();

        float s[8][4];
#pragma unroll
        for (int jb = 0; jb < 8; ++jb)
#pragma unroll
            for (int r = 0; r < 4; ++r) s[jb][r] = 0.0f;
#pragma unroll
        for (int kc = 0; kc < 6; ++kc) {
#pragma unroll
            for (int jb = 0; jb < 8; ++jb) {
                uint32_t b0 = f2tf32(Ks[8 * jb + g][8 * kc + tig]);
                uint32_t b1 = f2tf32(Ks[8 * jb + g][8 * kc + tig + 4]);
                mma_tf32(s[jb], qf[kc][0], qf[kc][1], qf[kc][2], qf[kc][3],
                         b0, b1);
            }
        }

        float cm0 = -1e30f, cm1 = -1e30f;
#pragma unroll
        for (int jb = 0; jb < 8; ++jb) {
            cm0 = fmaxf(cm0, fmaxf(s[jb][0], s[jb][1]));
            cm1 = fmaxf(cm1, fmaxf(s[jb][2], s[jb][3]));
        }
        cm0 = fmaxf(cm0, __shfl_xor_sync(0xffffffffu, cm0, 1));
        cm0 = fmaxf(cm0, __shfl_xor_sync(0xffffffffu, cm0, 2));
        cm1 = fmaxf(cm1, __shfl_xor_sync(0xffffffffu, cm1, 1));
        cm1 = fmaxf(cm1, __shfl_xor_sync(0xffffffffu, cm1, 2));
        float nm0 = fmaxf(mr0, cm0), nm1 = fmaxf(mr1, cm1);
        float corr0 = __expf(mr0 - nm0), corr1 = __expf(mr1 - nm1);
        float rs0 = 0.0f, rs1 = 0.0f;
#pragma unroll
        for (int jb = 0; jb < 8; ++jb) {
            s[jb][0] = __expf(s[jb][0] - nm0);
            s[jb][1] = __expf(s[jb][1] - nm0);
            rs0 += s[jb][0] + s[jb][1];
            s[jb][2] = __expf(s[jb][2] - nm1);
            s[jb][3] = __expf(s[jb][3] - nm1);
            rs1 += s[jb][2] + s[jb][3];
        }
        rs0 += __shfl_xor_sync(0xffffffffu, rs0, 1);
        rs0 += __shfl_xor_sync(0xffffffffu, rs0, 2);
        rs1 += __shfl_xor_sync(0xffffffffu, rs1, 1);
        rs1 += __shfl_xor_sync(0xffffffffu, rs1, 2);
        l0 = l0 * corr0 + rs0;
        l1 = l1 * corr1 + rs1;
        mr0 = nm0; mr1 = nm1;
#pragma unroll
        for (int nb = 0; nb < 6; ++nb) {
            of[nb][0] *= corr0; of[nb][1] *= corr0;
            of[nb][2] *= corr1; of[nb][3] *= corr1;
        }

#pragma unroll
        for (int jb = 0; jb < 8; ++jb) {
            *reinterpret_cast<float2*>(&QP[m0 + g][8 * jb + 2 * tig]) =
                make_float2(s[jb][0], s[jb][1]);
            *reinterpret_cast<float2*>(&QP[m0 + g + 8][8 * jb + 2 * tig]) =
                make_float2(s[jb][2], s[jb][3]);
        }
        __syncwarp();

#pragma unroll
        for (int pc = 0; pc < 8; ++pc) {
            uint32_t pa0 = f2tf32(QP[m0 + g][8 * pc + tig]);
            uint32_t pa1 = f2tf32(QP[m0 + g + 8][8 * pc + tig]);
            uint32_t pa2 = f2tf32(QP[m0 + g][8 * pc + tig + 4]);
            uint32_t pa3 = f2tf32(QP[m0 + g + 8][8 * pc + tig + 4]);
#pragma unroll
            for (int nb = 0; nb < 6; ++nb) {
                uint32_t b0 = f2tf32(Vt[8 * nb + g][8 * pc + tig]);
                uint32_t b1 = f2tf32(Vt[8 * nb + g][8 * pc + tig + 4]);
                mma_tf32(of[nb], pa0, pa1, pa2, pa3, b0, b1);
            }
        }
        __syncthreads();
    }

    float inv0 = 1.0f / l0, inv1 = 1.0f / l1;
    float* orow0 = xt + (size_t)(b * Nn + q0 + m0 + g) * Ee + h * DH;
    float* orow1 = orow0 + (size_t)8 * Ee;
#pragma unroll
    for (int nb = 0; nb < 6; ++nb) {
        int col = 8 * nb + 2 * tig;
        *reinterpret_cast<float2*>(&orow0[col]) =
            make_float2(of[nb][0] * inv0, of[nb][1] * inv0);
        *reinterpret_cast<float2*>(&orow1[col]) =
            make_float2(of[nb][2] * inv1, of[nb][3] * inv1);
    }
}

// ---------------------------------------------------------------------------
// Spatial attention: 192 threads, thread = (head, token). All lanes busy.
// ---------------------------------------------------------------------------
__global__ __launch_bounds__(192)
void spatial_attn(const float* __restrict__ qkv, float* __restrict__ xs)
{
    __shared__ float sh[8][3 * DH];   // per head: q[48] k[48] v[48]
    const int gBlk = blockIdx.x;
    const int tid = threadIdx.x;

    const float* base = qkv + (size_t)gBlk * E3;
    // load 1152 floats = 288 float4 with 192 threads
    for (int j = tid; j < 288; j += 192) {
        int sec = j / 96, w = j - sec * 96;
        int h = w / 12, i4 = w - h * 12;
        float4 v = *reinterpret_cast<const float4*>(
            &base[sec * Ee + h * DH + 4 * i4]);
        *reinterpret_cast<float4*>(&sh[h][sec * DH + 4 * i4]) = v;
    }
    __syncthreads();

    const int h = tid / NT, t = tid - h * NT;
    const float* q = sh[h];
    const float* k = sh[h] + DH;
    const float* v = sh[h] + 2 * DH;
    float q0 = q[t], q1 = q[NT + t];
    float s[NT];
    float mx = -1e30f;
#pragma unroll
    for (int u = 0; u < NT; ++u) {
        s[u] = fmaf(q1, k[NT + u], q0 * k[u]);
        mx = fmaxf(mx, s[u]);
    }
    float sum = 0.0f;
#pragma unroll
    for (int u = 0; u < NT; ++u) { s[u] = __expf(s[u] - mx); sum += s[u]; }
    float inv = 1.0f / sum;
    float o0 = 0.0f, o1 = 0.0f;
#pragma unroll
    for (int u = 0; u < NT; ++u) {
        o0 = fmaf(s[u], v[u], o0);
        o1 = fmaf(s[u], v[NT + u], o1);
    }
    float* op = xs + (size_t)gBlk * Ee + h * DH;
    op[t]      = o0 * inv;
    op[NT + t] = o1 * inv;
}

// ---------------------------------------------------------------------------
// Mean over frames of concat([x_t, x_s]) -> (B, 768). grid (B, 6) x 128.
// ---------------------------------------------------------------------------
__global__ __launch_bounds__(128)
void mean_concat(const float* __restrict__ xt, const float* __restrict__ xs,
                 float* __restrict__ alphaIn)
{
    const int b = blockIdx.x;
    const int j = blockIdx.y * 128 + threadIdx.x;
    const float* src = (j < Ee)
        ? xt + (size_t)b * Nn * Ee + j
        : xs + (size_t)b * Nn * Ee + (j - Ee);
    float acc = 0.0f;
#pragma unroll 8
    for (int n = 0; n < Nn; ++n) acc += src[(size_t)n * Ee];
    alphaIn[b * 2 * Ee + j] = acc * (1.0f / (float)Nn);
}

// ---------------------------------------------------------------------------
// Gating
// ---------------------------------------------------------------------------
__global__ __launch_bounds__(768)
void gate_kernel(const float* __restrict__ alphaIn, const float* __restrict__ Wts,
                 const float* __restrict__ bts,
                 float* __restrict__ g0, float* __restrict__ g1)
{
    __shared__ float a[768];
    __shared__ float val[768];
    const int b = blockIdx.x, t = threadIdx.x;
    a[t] = alphaIn[b * 768 + t];
    __syncthreads();
    float acc = bts[t];
    for (int k = 0; k < 768; ++k)
        acc = fmaf(a[k], Wts[(size_t)k * 768 + t], acc);
    val[t] = acc;
    __syncthreads();
    if (t < Ee) {
        float v0 = val[2 * t], v1 = val[2 * t + 1];
        float mx = fmaxf(v0, v1);
        float e0 = __expf(v0 - mx), e1 = __expf(v1 - mx);
        float inv = 1.0f / (e0 + e1);
        g0[b * Ee + t] = e0 * inv;
        g1[b * Ee + t] = e1 * inv;
    }
}

// ---------------------------------------------------------------------------
// Launch
// ---------------------------------------------------------------------------
extern "C" void kernel_launch(void* const* d_in, const int* in_sizes, int n_in,
                              void* d_out, int out_size)
{
    const float* x      = (const float*)d_in[0];
    const float* Wqkv_t = (const float*)d_in[1];
    const float* bqkv_t = (const float*)d_in[2];
    const float* Wqkv_s = (const float*)d_in[3];
    const float* bqkv_s = (const float*)d_in[4];
    const float* Wts    = (const float*)d_in[5];
    const float* bts    = (const float*)d_in[6];
    const float* Wfc_t  = (const float*)d_in[7];
    const float* bfc_t  = (const float*)d_in[8];
    const float* Wfc_s  = (const float*)d_in[9];
    const float* bfc_s  = (const float*)d_in[10];
    float* out = (float*)d_out;

    float *qkvT, *qkvS, *xt, *xs, *alphaIn, *g0, *g1;
    cudaGetSymbolAddress((void**)&qkvT,    g_qkv_t);
    cudaGetSymbolAddress((void**)&qkvS,    g_qkv_s);
    cudaGetSymbolAddress((void**)&xt,      g_xt);
    cudaGetSymbolAddress((void**)&xs,      g_xs);
    cudaGetSymbolAddress((void**)&alphaIn, g_alpha_in);
    cudaGetSymbolAddress((void**)&g0,      g_gate0);
    cudaGetSymbolAddress((void**)&g1,      g_gate1);

    cudaFuncSetAttribute(mma_gemm<0>,
                         cudaFuncAttributeMaxDynamicSharedMemorySize, GEMM_SMEM);
    cudaFuncSetAttribute(mma_gemm<1>,
                         cudaFuncAttributeMaxDynamicSharedMemorySize, GEMM_SMEM);

    // Fused QKV projections (both weight sets in one launch)
    mma_gemm<0><<<dim3(18, Mrows / 128), 256, GEMM_SMEM>>>(
        x, nullptr, Wqkv_t, Wqkv_s, nullptr, nullptr, bqkv_t, bqkv_s,
        qkvT, qkvS, INd, E3);

    // Attentions
    flash_tattn<<<dim3(Nn / 64, Hh, Bb), 128>>>(qkvT, xt);
    spatial_attn<<<Mrows, 192>>>(qkvS, xs);

    // Gating
    mean_concat<<<dim3(Bb, 6), 128>>>(xt, xs, alphaIn);
    gate_kernel<<<Bb, 768>>>(alphaIn, Wts, bts, g0, g1);

    // Fused gated output projection
    mma_gemm<1><<<dim3(OUTd / 128, Mrows / 128), 256, GEMM_SMEM>>>(
        xt, xs, Wfc_t, Wfc_s, g0, g1, bfc_t, bfc_s,
        out, nullptr, Ee, OUTd);
}

// round 8
// speedup vs baseline: 1.3312x; 1.3312x over previous
#include <cuda_runtime.h>
#include <cstdint>

// ---------------------------------------------------------------------------
// Problem constants
// ---------------------------------------------------------------------------
#define Bb   32
#define Nn   512
#define NT   24
#define Hh   8
#define DH   48
#define Ee   384          // H*DH
#define INd  768          // C*NT
#define OUTd 768
#define E3   1152         // 3*E
#define Mrows (Bb*Nn)     // 16384

// ---------------------------------------------------------------------------
// Scratch (device globals)
// ---------------------------------------------------------------------------
__device__ float g_qkv_t[(size_t)Mrows * E3];
__device__ float g_qkv_s[(size_t)Mrows * E3];
__device__ float g_xt[(size_t)Mrows * Ee];
__device__ float g_xs[(size_t)Mrows * Ee];
__device__ float g_alpha_part[4 * Bb * 2 * Ee];
__device__ float g_alpha_in[Bb * 2 * Ee];
__device__ float g_gate0[Bb * Ee];
__device__ float g_gate1[Bb * Ee];

// ---------------------------------------------------------------------------
// tf32 / cp.async helpers
// ---------------------------------------------------------------------------
__device__ __forceinline__ uint32_t f2tf32(float f) {
    uint32_t o;
    asm("cvt.rna.tf32.f32 %0, %1;" : "=r"(o) : "f"(f));
    return o;
}

__device__ __forceinline__ void mma_tf32(float c[4],
                                         uint32_t a0, uint32_t a1,
                                         uint32_t a2, uint32_t a3,
                                         uint32_t b0, uint32_t b1) {
    asm volatile(
        "mma.sync.aligned.m16n8k8.row.col.f32.tf32.tf32.f32 "
        "{%0,%1,%2,%3}, {%4,%5,%6,%7}, {%8,%9}, {%0,%1,%2,%3};\n"
        : "+f"(c[0]), "+f"(c[1]), "+f"(c[2]), "+f"(c[3])
        : "r"(a0), "r"(a1), "r"(a2), "r"(a3), "r"(b0), "r"(b1));
}

__device__ __forceinline__ void cp_async16(void* smem_dst, const void* gmem_src) {
    uint32_t d = (uint32_t)__cvta_generic_to_shared(smem_dst);
    asm volatile("cp.async.cg.shared.global [%0], [%1], 16;\n"
                 :: "r"(d), "l"(gmem_src));
}
__device__ __forceinline__ void cp_async_commit() {
    asm volatile("cp.async.commit_group;\n");
}
__device__ __forceinline__ void cp_async_wait_all() {
    asm volatile("cp.async.wait_group 0;\n");
}

// ---------------------------------------------------------------------------
// tf32 mma.sync GEMM, 128x128 tile, BK=32, 256 threads, double buffered,
// READ-SIDE tf32 conversion (cvt interleaves with MMA issue; one sync/chunk).
//
// MODE 0 (dual-N QKV): bx<9 -> C0 = A @ W0 + bias0 ; bx>=9 -> C1 = A @ W1 + bias1
// MODE 1 (fused out):  C = (A0*g0[b]) @ W0 + (A1*g1[b]) @ W1 + bias0 + bias1
//         (gate applied to B fragment scalars, == A*diag(g) @ W)
// ---------------------------------------------------------------------------
template <int MODE>
__global__ __launch_bounds__(256, 2)
void mma_gemm(const float* __restrict__ A0, const float* __restrict__ A1,
              const float* __restrict__ W0, const float* __restrict__ W1,
              const float* __restrict__ g0p, const float* __restrict__ g1p,
              const float* __restrict__ bias0, const float* __restrict__ bias1,
              float* __restrict__ C0, float* __restrict__ C1,
              int Kd, int Nd)
{
    extern __shared__ float smem[];
    float (*As)[128][36] = reinterpret_cast<float(*)[128][36]>(smem);
    float (*Bs)[32][132] = reinterpret_cast<float(*)[32][132]>(smem + 2 * 128 * 36);

    const int tid  = threadIdx.x;
    const int lane = tid & 31;
    const int warp = tid >> 5;
    const int g    = lane >> 2;
    const int tig  = lane & 3;
    const int warpM = (warp & 1) * 64;
    const int warpN = (warp >> 1) * 32;

    const int rowBase = blockIdx.y * 128;
    const int bIdx = rowBase >> 9;

    int colBase, half = 0;
    const float* Wsel;
    const float* biasSel;
    float* Csel;
    if (MODE == 0) {
        half = (blockIdx.x >= 9);
        colBase = (blockIdx.x - half * 9) * 128;
        Wsel = half ? W1 : W0;
        biasSel = half ? bias1 : bias0;
        Csel = half ? C1 : C0;
    } else {
        colBase = blockIdx.x * 128;
        Wsel = nullptr; biasSel = nullptr; Csel = C0;
    }

    const int perPass = Kd >> 5;
    const int nChunks = (MODE == 1) ? 2 * perPass : perPass;

    auto issueLoad = [&](int c, int buf) {
        int pass = (MODE == 1) ? (c / perPass) : 0;
        int k0 = ((MODE == 1) ? (c - pass * perPass) : c) << 5;
        const float* A = (MODE == 1 && pass) ? A1 : A0;
        const float* W = (MODE == 0) ? Wsel : (pass ? W1 : W0);
        // A tile: 128 x 32 floats = 1024 float4
#pragma unroll
        for (int i = 0; i < 4; ++i) {
            int idx = i * 256 + tid;
            int r = idx >> 3, c4 = idx & 7;
            cp_async16(&As[buf][r][c4 * 4],
                       &A[(size_t)(rowBase + r) * Kd + k0 + c4 * 4]);
        }
        // B tile: 32 x 128 floats = 1024 float4 (W is [K][Nd] row-major)
#pragma unroll
        for (int i = 0; i < 4; ++i) {
            int idx = i * 256 + tid;
            int r = idx >> 5, c4 = idx & 31;
            cp_async16(&Bs[buf][r][c4 * 4],
                       &W[(size_t)(k0 + r) * Nd + colBase + c4 * 4]);
        }
        cp_async_commit();
    };

    float acc[4][4][4];
#pragma unroll
    for (int i = 0; i < 4; ++i)
#pragma unroll
        for (int j = 0; j < 4; ++j)
#pragma unroll
            for (int r = 0; r < 4; ++r) acc[i][j][r] = 0.0f;

    issueLoad(0, 0);

    for (int c = 0; c < nChunks; ++c) {
        const int buf = c & 1;
        cp_async_wait_all();
        __syncthreads();
        if (c + 1 < nChunks) issueLoad(c + 1, buf ^ 1);

        const float* gate = nullptr;
        int kBase = 0;
        if (MODE == 1) {
            int pass = c / perPass;
            kBase = (c - pass * perPass) << 5;
            gate = (pass ? g1p : g0p) + bIdx * Ee + kBase;
        }

        // ---- compute: 4 kk-slices of 8, read-side conversion ----
#pragma unroll
        for (int kk = 0; kk < 32; kk += 8) {
            uint32_t af[4][4];
#pragma unroll
            for (int i = 0; i < 4; ++i) {
                int m0 = warpM + 16 * i;
                af[i][0] = f2tf32(As[buf][m0 + g][kk + tig]);
                af[i][1] = f2tf32(As[buf][m0 + g + 8][kk + tig]);
                af[i][2] = f2tf32(As[buf][m0 + g][kk + tig + 4]);
                af[i][3] = f2tf32(As[buf][m0 + g + 8][kk + tig + 4]);
            }
            float gv0 = 1.0f, gv1 = 1.0f;
            if (MODE == 1) {
                gv0 = gate[kk + tig];
                gv1 = gate[kk + tig + 4];
            }
            uint32_t bf[4][2];
#pragma unroll
            for (int j = 0; j < 4; ++j) {
                int n0 = warpN + 8 * j;
                float v0 = Bs[buf][kk + tig][n0 + g];
                float v1 = Bs[buf][kk + tig + 4][n0 + g];
                if (MODE == 1) { v0 *= gv0; v1 *= gv1; }
                bf[j][0] = f2tf32(v0);
                bf[j][1] = f2tf32(v1);
            }
#pragma unroll
            for (int i = 0; i < 4; ++i)
#pragma unroll
                for (int j = 0; j < 4; ++j)
                    mma_tf32(acc[i][j], af[i][0], af[i][1], af[i][2],
                             af[i][3], bf[j][0], bf[j][1]);
        }
    }
    __syncthreads();

    // ---- epilogue ----
#pragma unroll
    for (int i = 0; i < 4; ++i) {
#pragma unroll
        for (int j = 0; j < 4; ++j) {
            int col = colBase + warpN + 8 * j + 2 * tig;
            float bsum0, bsum1;
            if (MODE == 1) {
                bsum0 = bias0[col] + bias1[col];
                bsum1 = bias0[col + 1] + bias1[col + 1];
            } else {
                bsum0 = biasSel[col];
                bsum1 = biasSel[col + 1];
            }
            int row0 = rowBase + warpM + 16 * i + g;
            float* Cw = (MODE == 0) ? Csel : C0;
            float2 o0 = make_float2(acc[i][j][0] + bsum0, acc[i][j][1] + bsum1);
            *reinterpret_cast<float2*>(&Cw[(size_t)row0 * Nd + col]) = o0;
            float2 o1 = make_float2(acc[i][j][2] + bsum0, acc[i][j][3] + bsum1);
            *reinterpret_cast<float2*>(&Cw[(size_t)(row0 + 8) * Nd + col]) = o1;
        }
    }
}

#define GEMM_SMEM (2 * (128 * 36 + 32 * 132) * 4)

// ---------------------------------------------------------------------------
// Flash temporal attention (unchanged, passing)
// ---------------------------------------------------------------------------
__global__ __launch_bounds__(128)
void flash_tattn(const float* __restrict__ qkv, float* __restrict__ xt)
{
    __shared__ float QP[64][68];
    __shared__ float Ks[64][52];
    __shared__ float Vt[48][68];

    const int b = blockIdx.z, h = blockIdx.y;
    const int q0 = blockIdx.x * 64;
    const int tid = threadIdx.x;
    const int warp = tid >> 5, lane = tid & 31;
    const int g = lane >> 2, tig = lane & 3;
    const int m0 = warp * 16;
    const float scale = 0.14433756729740643f;

    const float* base = qkv + (size_t)(b * Nn) * E3 + h * DH;

    for (int i = tid; i < 64 * 12; i += 128) {
        int r = i / 12, f = i % 12;
        float4 v = *reinterpret_cast<const float4*>(
            &base[(size_t)(q0 + r) * E3 + 4 * f]);
        v.x *= scale; v.y *= scale; v.z *= scale; v.w *= scale;
        *reinterpret_cast<float4*>(&QP[r][4 * f]) = v;
    }
    __syncthreads();

    uint32_t qf[6][4];
#pragma unroll
    for (int kc = 0; kc < 6; ++kc) {
        qf[kc][0] = f2tf32(QP[m0 + g][8 * kc + tig]);
        qf[kc][1] = f2tf32(QP[m0 + g + 8][8 * kc + tig]);
        qf[kc][2] = f2tf32(QP[m0 + g][8 * kc + tig + 4]);
        qf[kc][3] = f2tf32(QP[m0 + g + 8][8 * kc + tig + 4]);
    }
    __syncthreads();

    float of[6][4];
#pragma unroll
    for (int nb = 0; nb < 6; ++nb)
#pragma unroll
        for (int r = 0; r < 4; ++r) of[nb][r] = 0.0f;
    float mr0 = -1e30f, mr1 = -1e30f, l0 = 0.0f, l1 = 0.0f;

    for (int c0 = 0; c0 < Nn; c0 += 64) {
        for (int i = tid; i < 64 * 12; i += 128) {
            int r = i / 12, f = i % 12;
            const float* src = &base[(size_t)(c0 + r) * E3 + 4 * f];
            float4 kv = *reinterpret_cast<const float4*>(src + Ee);
            *reinterpret_cast<float4*>(&Ks[r][4 * f]) = kv;
            float4 vv = *reinterpret_cast<const float4*>(src + 2 * Ee);
            Vt[4 * f + 0][r] = vv.x;
            Vt[4 * f + 1][r] = vv.y;
            Vt[4 * f + 2][r] = vv.z;
            Vt[4 * f + 3][r] = vv.w;
        }
        __syncthreads();

        float s[8][4];
#pragma unroll
        for (int jb = 0; jb < 8; ++jb)
#pragma unroll
            for (int r = 0; r < 4; ++r) s[jb][r] = 0.0f;
#pragma unroll
        for (int kc = 0; kc < 6; ++kc) {
#pragma unroll
            for (int jb = 0; jb < 8; ++jb) {
                uint32_t b0 = f2tf32(Ks[8 * jb + g][8 * kc + tig]);
                uint32_t b1 = f2tf32(Ks[8 * jb + g][8 * kc + tig + 4]);
                mma_tf32(s[jb], qf[kc][0], qf[kc][1], qf[kc][2], qf[kc][3],
                         b0, b1);
            }
        }

        float cm0 = -1e30f, cm1 = -1e30f;
#pragma unroll
        for (int jb = 0; jb < 8; ++jb) {
            cm0 = fmaxf(cm0, fmaxf(s[jb][0], s[jb][1]));
            cm1 = fmaxf(cm1, fmaxf(s[jb][2], s[jb][3]));
        }
        cm0 = fmaxf(cm0, __shfl_xor_sync(0xffffffffu, cm0, 1));
        cm0 = fmaxf(cm0, __shfl_xor_sync(0xffffffffu, cm0, 2));
        cm1 = fmaxf(cm1, __shfl_xor_sync(0xffffffffu, cm1, 1));
        cm1 = fmaxf(cm1, __shfl_xor_sync(0xffffffffu, cm1, 2));
        float nm0 = fmaxf(mr0, cm0), nm1 = fmaxf(mr1, cm1);
        float corr0 = __expf(mr0 - nm0), corr1 = __expf(mr1 - nm1);
        float rs0 = 0.0f, rs1 = 0.0f;
#pragma unroll
        for (int jb = 0; jb < 8; ++jb) {
            s[jb][0] = __expf(s[jb][0] - nm0);
            s[jb][1] = __expf(s[jb][1] - nm0);
            rs0 += s[jb][0] + s[jb][1];
            s[jb][2] = __expf(s[jb][2] - nm1);
            s[jb][3] = __expf(s[jb][3] - nm1);
            rs1 += s[jb][2] + s[jb][3];
        }
        rs0 += __shfl_xor_sync(0xffffffffu, rs0, 1);
        rs0 += __shfl_xor_sync(0xffffffffu, rs0, 2);
        rs1 += __shfl_xor_sync(0xffffffffu, rs1, 1);
        rs1 += __shfl_xor_sync(0xffffffffu, rs1, 2);
        l0 = l0 * corr0 + rs0;
        l1 = l1 * corr1 + rs1;
        mr0 = nm0; mr1 = nm1;
#pragma unroll
        for (int nb = 0; nb < 6; ++nb) {
            of[nb][0] *= corr0; of[nb][1] *= corr0;
            of[nb][2] *= corr1; of[nb][3] *= corr1;
        }

#pragma unroll
        for (int jb = 0; jb < 8; ++jb) {
            *reinterpret_cast<float2*>(&QP[m0 + g][8 * jb + 2 * tig]) =
                make_float2(s[jb][0], s[jb][1]);
            *reinterpret_cast<float2*>(&QP[m0 + g + 8][8 * jb + 2 * tig]) =
                make_float2(s[jb][2], s[jb][3]);
        }
        __syncwarp();

#pragma unroll
        for (int pc = 0; pc < 8; ++pc) {
            uint32_t pa0 = f2tf32(QP[m0 + g][8 * pc + tig]);
            uint32_t pa1 = f2tf32(QP[m0 + g + 8][8 * pc + tig]);
            uint32_t pa2 = f2tf32(QP[m0 + g][8 * pc + tig + 4]);
            uint32_t pa3 = f2tf32(QP[m0 + g + 8][8 * pc + tig + 4]);
#pragma unroll
            for (int nb = 0; nb < 6; ++nb) {
                uint32_t b0 = f2tf32(Vt[8 * nb + g][8 * pc + tig]);
                uint32_t b1 = f2tf32(Vt[8 * nb + g][8 * pc + tig + 4]);
                mma_tf32(of[nb], pa0, pa1, pa2, pa3, b0, b1);
            }
        }
        __syncthreads();
    }

    float inv0 = 1.0f / l0, inv1 = 1.0f / l1;
    float* orow0 = xt + (size_t)(b * Nn + q0 + m0 + g) * Ee + h * DH;
    float* orow1 = orow0 + (size_t)8 * Ee;
#pragma unroll
    for (int nb = 0; nb < 6; ++nb) {
        int col = 8 * nb + 2 * tig;
        *reinterpret_cast<float2*>(&orow0[col]) =
            make_float2(of[nb][0] * inv0, of[nb][1] * inv0);
        *reinterpret_cast<float2*>(&orow1[col]) =
            make_float2(of[nb][2] * inv1, of[nb][3] * inv1);
    }
}

// ---------------------------------------------------------------------------
// Spatial attention: 192 threads, thread = (head, token).
// ---------------------------------------------------------------------------
__global__ __launch_bounds__(192)
void spatial_attn(const float* __restrict__ qkv, float* __restrict__ xs)
{
    __shared__ float sh[8][3 * DH];
    const int gBlk = blockIdx.x;
    const int tid = threadIdx.x;

    const float* base = qkv + (size_t)gBlk * E3;
    for (int j = tid; j < 288; j += 192) {
        int sec = j / 96, w = j - sec * 96;
        int h = w / 12, i4 = w - h * 12;
        float4 v = *reinterpret_cast<const float4*>(
            &base[sec * Ee + h * DH + 4 * i4]);
        *reinterpret_cast<float4*>(&sh[h][sec * DH + 4 * i4]) = v;
    }
    __syncthreads();

    const int h = tid / NT, t = tid - h * NT;
    const float* q = sh[h];
    const float* k = sh[h] + DH;
    const float* v = sh[h] + 2 * DH;
    float q0 = q[t], q1 = q[NT + t];
    float s[NT];
    float mx = -1e30f;
#pragma unroll
    for (int u = 0; u < NT; ++u) {
        s[u] = fmaf(q1, k[NT + u], q0 * k[u]);
        mx = fmaxf(mx, s[u]);
    }
    float sum = 0.0f;
#pragma unroll
    for (int u = 0; u < NT; ++u) { s[u] = __expf(s[u] - mx); sum += s[u]; }
    float inv = 1.0f / sum;
    float o0 = 0.0f, o1 = 0.0f;
#pragma unroll
    for (int u = 0; u < NT; ++u) {
        o0 = fmaf(s[u], v[u], o0);
        o1 = fmaf(s[u], v[NT + u], o1);
    }
    float* op = xs + (size_t)gBlk * Ee + h * DH;
    op[t]      = o0 * inv;
    op[NT + t] = o1 * inv;
}

// ---------------------------------------------------------------------------
// Mean stage 1: partial sums over 128-frame slices.
// grid (B, 6, 4), block 128. part[z][b][j] = sum_{n in slice z} src[n][j]
// ---------------------------------------------------------------------------
__global__ __launch_bounds__(128)
void mean_part(const float* __restrict__ xt, const float* __restrict__ xs,
               float* __restrict__ part)
{
    const int b = blockIdx.x;
    const int j = blockIdx.y * 128 + threadIdx.x;   // 0..767
    const int z = blockIdx.z;
    const float* src = (j < Ee)
        ? xt + (size_t)b * Nn * Ee + (size_t)(z * 128) * Ee + j
        : xs + (size_t)b * Nn * Ee + (size_t)(z * 128) * Ee + (j - Ee);
    float acc = 0.0f;
#pragma unroll 8
    for (int n = 0; n < 128; ++n) acc += src[(size_t)n * Ee];
    part[((size_t)z * Bb + b) * (2 * Ee) + j] = acc;
}

// ---------------------------------------------------------------------------
// Mean stage 2: reduce 4 partials -> alphaIn. grid (B, 6), block 128.
// ---------------------------------------------------------------------------
__global__ __launch_bounds__(128)
void mean_reduce(const float* __restrict__ part, float* __restrict__ alphaIn)
{
    const int b = blockIdx.x;
    const int j = blockIdx.y * 128 + threadIdx.x;
    float acc = 0.0f;
#pragma unroll
    for (int z = 0; z < 4; ++z)
        acc += part[((size_t)z * Bb + b) * (2 * Ee) + j];
    alphaIn[b * 2 * Ee + j] = acc * (1.0f / (float)Nn);
}

// ---------------------------------------------------------------------------
// Gating
// ---------------------------------------------------------------------------
__global__ __launch_bounds__(768)
void gate_kernel(const float* __restrict__ alphaIn, const float* __restrict__ Wts,
                 const float* __restrict__ bts,
                 float* __restrict__ g0, float* __restrict__ g1)
{
    __shared__ float a[768];
    __shared__ float val[768];
    const int b = blockIdx.x, t = threadIdx.x;
    a[t] = alphaIn[b * 768 + t];
    __syncthreads();
    float acc = bts[t];
    for (int k = 0; k < 768; ++k)
        acc = fmaf(a[k], Wts[(size_t)k * 768 + t], acc);
    val[t] = acc;
    __syncthreads();
    if (t < Ee) {
        float v0 = val[2 * t], v1 = val[2 * t + 1];
        float mx = fmaxf(v0, v1);
        float e0 = __expf(v0 - mx), e1 = __expf(v1 - mx);
        float inv = 1.0f / (e0 + e1);
        g0[b * Ee + t] = e0 * inv;
        g1[b * Ee + t] = e1 * inv;
    }
}

// ---------------------------------------------------------------------------
// Launch
// ---------------------------------------------------------------------------
extern "C" void kernel_launch(void* const* d_in, const int* in_sizes, int n_in,
                              void* d_out, int out_size)
{
    const float* x      = (const float*)d_in[0];
    const float* Wqkv_t = (const float*)d_in[1];
    const float* bqkv_t = (const float*)d_in[2];
    const float* Wqkv_s = (const float*)d_in[3];
    const float* bqkv_s = (const float*)d_in[4];
    const float* Wts    = (const float*)d_in[5];
    const float* bts    = (const float*)d_in[6];
    const float* Wfc_t  = (const float*)d_in[7];
    const float* bfc_t  = (const float*)d_in[8];
    const float* Wfc_s  = (const float*)d_in[9];
    const float* bfc_s  = (const float*)d_in[10];
    float* out = (float*)d_out;

    float *qkvT, *qkvS, *xt, *xs, *part, *alphaIn, *g0, *g1;
    cudaGetSymbolAddress((void**)&qkvT,    g_qkv_t);
    cudaGetSymbolAddress((void**)&qkvS,    g_qkv_s);
    cudaGetSymbolAddress((void**)&xt,      g_xt);
    cudaGetSymbolAddress((void**)&xs,      g_xs);
    cudaGetSymbolAddress((void**)&part,    g_alpha_part);
    cudaGetSymbolAddress((void**)&alphaIn, g_alpha_in);
    cudaGetSymbolAddress((void**)&g0,      g_gate0);
    cudaGetSymbolAddress((void**)&g1,      g_gate1);

    cudaFuncSetAttribute(mma_gemm<0>,
                         cudaFuncAttributeMaxDynamicSharedMemorySize, GEMM_SMEM);
    cudaFuncSetAttribute(mma_gemm<1>,
                         cudaFuncAttributeMaxDynamicSharedMemorySize, GEMM_SMEM);

    // Fused QKV projections (both weight sets in one launch)
    mma_gemm<0><<<dim3(18, Mrows / 128), 256, GEMM_SMEM>>>(
        x, nullptr, Wqkv_t, Wqkv_s, nullptr, nullptr, bqkv_t, bqkv_s,
        qkvT, qkvS, INd, E3);

    // Attentions
    flash_tattn<<<dim3(Nn / 64, Hh, Bb), 128>>>(qkvT, xt);
    spatial_attn<<<Mrows, 192>>>(qkvS, xs);

    // Gating (split-n mean, deterministic two-stage)
    mean_part<<<dim3(Bb, 6, 4), 128>>>(xt, xs, part);
    mean_reduce<<<dim3(Bb, 6), 128>>>(part, alphaIn);
    gate_kernel<<<Bb, 768>>>(alphaIn, Wts, bts, g0, g1);

    // Fused gated output projection
    mma_gemm<1><<<dim3(OUTd / 128, Mrows / 128), 256, GEMM_SMEM>>>(
        xt, xs, Wfc_t, Wfc_s, g0, g1, bfc_t, bfc_s,
        out, nullptr, Ee, OUTd);
}

// round 9
// speedup vs baseline: 1.4203x; 1.0669x over previous
#include <cuda_runtime.h>
#include <cuda_fp16.h>
#include <cstdint>

// ---------------------------------------------------------------------------
// Problem constants
// ---------------------------------------------------------------------------
#define Bb   32
#define Nn   512
#define NT   24
#define Hh   8
#define DH   48
#define Ee   384          // H*DH
#define INd  768          // C*NT
#define OUTd 768
#define E3   1152         // 3*E
#define Mrows (Bb*Nn)     // 16384

// ---------------------------------------------------------------------------
// Scratch (device globals)
// ---------------------------------------------------------------------------
__device__ float g_qkv_t[(size_t)Mrows * E3];
__device__ float g_qkv_s[(size_t)Mrows * E3];
__device__ float g_xt[(size_t)Mrows * Ee];
__device__ float g_xs[(size_t)Mrows * Ee];
__device__ float g_alpha_part[4 * Bb * 2 * Ee];
__device__ float g_alpha_in[Bb * 2 * Ee];
__device__ float g_gate0[Bb * Ee];
__device__ float g_gate1[Bb * Ee];

// ---------------------------------------------------------------------------
// fp16 mma / cp.async helpers
// ---------------------------------------------------------------------------
__device__ __forceinline__ uint32_t packh2(float lo, float hi) {
    __half2 h = __floats2half2_rn(lo, hi);
    return *reinterpret_cast<uint32_t*>(&h);
}

__device__ __forceinline__ void mma_f16(float c[4],
                                        uint32_t a0, uint32_t a1,
                                        uint32_t a2, uint32_t a3,
                                        uint32_t b0, uint32_t b1) {
    asm volatile(
        "mma.sync.aligned.m16n8k16.row.col.f32.f16.f16.f32 "
        "{%0,%1,%2,%3}, {%4,%5,%6,%7}, {%8,%9}, {%0,%1,%2,%3};\n"
        : "+f"(c[0]), "+f"(c[1]), "+f"(c[2]), "+f"(c[3])
        : "r"(a0), "r"(a1), "r"(a2), "r"(a3), "r"(b0), "r"(b1));
}

__device__ __forceinline__ void cp_async16(void* smem_dst, const void* gmem_src) {
    uint32_t d = (uint32_t)__cvta_generic_to_shared(smem_dst);
    asm volatile("cp.async.cg.shared.global [%0], [%1], 16;\n"
                 :: "r"(d), "l"(gmem_src));
}
__device__ __forceinline__ void cp_async_commit() {
    asm volatile("cp.async.commit_group;\n");
}
__device__ __forceinline__ void cp_async_wait_all() {
    asm volatile("cp.async.wait_group 0;\n");
}

// ---------------------------------------------------------------------------
// fp16 mma.sync GEMM, 128x128 tile, BK=32, 256 threads, double buffered,
// fp32 smem staging + read-side f16x2 packing (cvt interleaves with MMA).
//
// MODE 0 (dual-N QKV): bx<9 -> C0 = A @ W0 + bias0 ; bx>=9 -> C1 = A @ W1 + bias1
// MODE 1 (fused out):  C = (A0*g0[b]) @ W0 + (A1*g1[b]) @ W1 + bias0 + bias1
// ---------------------------------------------------------------------------
template <int MODE>
__global__ __launch_bounds__(256, 2)
void mma_gemm(const float* __restrict__ A0, const float* __restrict__ A1,
              const float* __restrict__ W0, const float* __restrict__ W1,
              const float* __restrict__ g0p, const float* __restrict__ g1p,
              const float* __restrict__ bias0, const float* __restrict__ bias1,
              float* __restrict__ C0, float* __restrict__ C1,
              int Kd, int Nd)
{
    extern __shared__ float smem[];
    float (*As)[128][36] = reinterpret_cast<float(*)[128][36]>(smem);
    float (*Bs)[32][132] = reinterpret_cast<float(*)[32][132]>(smem + 2 * 128 * 36);

    const int tid  = threadIdx.x;
    const int lane = tid & 31;
    const int warp = tid >> 5;
    const int g    = lane >> 2;
    const int tig  = lane & 3;
    const int warpM = (warp & 1) * 64;
    const int warpN = (warp >> 1) * 32;

    const int rowBase = blockIdx.y * 128;
    const int bIdx = rowBase >> 9;

    int colBase, half = 0;
    const float* Wsel;
    const float* biasSel;
    float* Csel;
    if (MODE == 0) {
        half = (blockIdx.x >= 9);
        colBase = (blockIdx.x - half * 9) * 128;
        Wsel = half ? W1 : W0;
        biasSel = half ? bias1 : bias0;
        Csel = half ? C1 : C0;
    } else {
        colBase = blockIdx.x * 128;
        Wsel = nullptr; biasSel = nullptr; Csel = C0;
    }

    const int perPass = Kd >> 5;
    const int nChunks = (MODE == 1) ? 2 * perPass : perPass;

    auto issueLoad = [&](int c, int buf) {
        int pass = (MODE == 1) ? (c / perPass) : 0;
        int k0 = ((MODE == 1) ? (c - pass * perPass) : c) << 5;
        const float* A = (MODE == 1 && pass) ? A1 : A0;
        const float* W = (MODE == 0) ? Wsel : (pass ? W1 : W0);
#pragma unroll
        for (int i = 0; i < 4; ++i) {
            int idx = i * 256 + tid;
            int r = idx >> 3, c4 = idx & 7;
            cp_async16(&As[buf][r][c4 * 4],
                       &A[(size_t)(rowBase + r) * Kd + k0 + c4 * 4]);
        }
#pragma unroll
        for (int i = 0; i < 4; ++i) {
            int idx = i * 256 + tid;
            int r = idx >> 5, c4 = idx & 31;
            cp_async16(&Bs[buf][r][c4 * 4],
                       &W[(size_t)(k0 + r) * Nd + colBase + c4 * 4]);
        }
        cp_async_commit();
    };

    float acc[4][4][4];
#pragma unroll
    for (int i = 0; i < 4; ++i)
#pragma unroll
        for (int j = 0; j < 4; ++j)
#pragma unroll
            for (int r = 0; r < 4; ++r) acc[i][j][r] = 0.0f;

    issueLoad(0, 0);

    for (int c = 0; c < nChunks; ++c) {
        const int buf = c & 1;
        cp_async_wait_all();
        __syncthreads();
        if (c + 1 < nChunks) issueLoad(c + 1, buf ^ 1);

        const float* gate = nullptr;
        if (MODE == 1) {
            int pass = c / perPass;
            int kBase = (c - pass * perPass) << 5;
            gate = (pass ? g1p : g0p) + bIdx * Ee + kBase;
        }

        // ---- compute: 2 kk-slices of 16, fp16 m16n8k16 ----
#pragma unroll
        for (int kk = 0; kk < 32; kk += 16) {
            const int kA = kk + 2 * tig;      // first k of low pair
            uint32_t af[4][4];
#pragma unroll
            for (int i = 0; i < 4; ++i) {
                int m0 = warpM + 16 * i;
                af[i][0] = packh2(As[buf][m0 + g][kA],
                                  As[buf][m0 + g][kA + 1]);
                af[i][1] = packh2(As[buf][m0 + g + 8][kA],
                                  As[buf][m0 + g + 8][kA + 1]);
                af[i][2] = packh2(As[buf][m0 + g][kA + 8],
                                  As[buf][m0 + g][kA + 9]);
                af[i][3] = packh2(As[buf][m0 + g + 8][kA + 8],
                                  As[buf][m0 + g + 8][kA + 9]);
            }
            float gl0 = 1.0f, gl1 = 1.0f, gh0 = 1.0f, gh1 = 1.0f;
            if (MODE == 1) {
                gl0 = gate[kA];     gl1 = gate[kA + 1];
                gh0 = gate[kA + 8]; gh1 = gate[kA + 9];
            }
            uint32_t bf[4][2];
#pragma unroll
            for (int j = 0; j < 4; ++j) {
                int n0 = warpN + 8 * j + g;
                float v0 = Bs[buf][kA][n0];
                float v1 = Bs[buf][kA + 1][n0];
                float v2 = Bs[buf][kA + 8][n0];
                float v3 = Bs[buf][kA + 9][n0];
                if (MODE == 1) { v0 *= gl0; v1 *= gl1; v2 *= gh0; v3 *= gh1; }
                bf[j][0] = packh2(v0, v1);
                bf[j][1] = packh2(v2, v3);
            }
#pragma unroll
            for (int i = 0; i < 4; ++i)
#pragma unroll
                for (int j = 0; j < 4; ++j)
                    mma_f16(acc[i][j], af[i][0], af[i][1], af[i][2],
                            af[i][3], bf[j][0], bf[j][1]);
        }
    }
    __syncthreads();

    // ---- epilogue (C layout identical to tf32 path) ----
#pragma unroll
    for (int i = 0; i < 4; ++i) {
#pragma unroll
        for (int j = 0; j < 4; ++j) {
            int col = colBase + warpN + 8 * j + 2 * tig;
            float bsum0, bsum1;
            if (MODE == 1) {
                bsum0 = bias0[col] + bias1[col];
                bsum1 = bias0[col + 1] + bias1[col + 1];
            } else {
                bsum0 = biasSel[col];
                bsum1 = biasSel[col + 1];
            }
            int row0 = rowBase + warpM + 16 * i + g;
            float* Cw = (MODE == 0) ? Csel : C0;
            float2 o0 = make_float2(acc[i][j][0] + bsum0, acc[i][j][1] + bsum1);
            *reinterpret_cast<float2*>(&Cw[(size_t)row0 * Nd + col]) = o0;
            float2 o1 = make_float2(acc[i][j][2] + bsum0, acc[i][j][3] + bsum1);
            *reinterpret_cast<float2*>(&Cw[(size_t)(row0 + 8) * Nd + col]) = o1;
        }
    }
}

#define GEMM_SMEM (2 * (128 * 36 + 32 * 132) * 4)

// ---------------------------------------------------------------------------
// Flash temporal attention, fp16 m16n8k16 (fp32 accumulate, fp32 softmax).
// CTA = (64 q-rows, head, batch); 4 warps; warp owns 16 q-rows.
// ---------------------------------------------------------------------------
__global__ __launch_bounds__(128)
void flash_tattn(const float* __restrict__ qkv, float* __restrict__ xt)
{
    __shared__ float QP[64][68];   // Q staging, then P
    __shared__ float Ks[64][52];   // K chunk [key][dim]
    __shared__ float Vt[48][68];   // V chunk transposed [dim][key]

    const int b = blockIdx.z, h = blockIdx.y;
    const int q0 = blockIdx.x * 64;
    const int tid = threadIdx.x;
    const int warp = tid >> 5, lane = tid & 31;
    const int g = lane >> 2, tig = lane & 3;
    const int m0 = warp * 16;
    const float scale = 0.14433756729740643f;

    const float* base = qkv + (size_t)(b * Nn) * E3 + h * DH;

    for (int i = tid; i < 64 * 12; i += 128) {
        int r = i / 12, f = i % 12;
        float4 v = *reinterpret_cast<const float4*>(
            &base[(size_t)(q0 + r) * E3 + 4 * f]);
        v.x *= scale; v.y *= scale; v.z *= scale; v.w *= scale;
        *reinterpret_cast<float4*>(&QP[r][4 * f]) = v;
    }
    __syncthreads();

    // ---- Q fragments: 3 k-chunks of 16 (DH=48), packed fp16 ----
    uint32_t qf[3][4];
#pragma unroll
    for (int kc = 0; kc < 3; ++kc) {
        int kA = 16 * kc + 2 * tig;
        qf[kc][0] = packh2(QP[m0 + g][kA],     QP[m0 + g][kA + 1]);
        qf[kc][1] = packh2(QP[m0 + g + 8][kA], QP[m0 + g + 8][kA + 1]);
        qf[kc][2] = packh2(QP[m0 + g][kA + 8], QP[m0 + g][kA + 9]);
        qf[kc][3] = packh2(QP[m0 + g + 8][kA + 8], QP[m0 + g + 8][kA + 9]);
    }
    __syncthreads();

    float of[6][4];
#pragma unroll
    for (int nb = 0; nb < 6; ++nb)
#pragma unroll
        for (int r = 0; r < 4; ++r) of[nb][r] = 0.0f;
    float mr0 = -1e30f, mr1 = -1e30f, l0 = 0.0f, l1 = 0.0f;

    for (int c0 = 0; c0 < Nn; c0 += 64) {
        for (int i = tid; i < 64 * 12; i += 128) {
            int r = i / 12, f = i % 12;
            const float* src = &base[(size_t)(c0 + r) * E3 + 4 * f];
            float4 kv = *reinterpret_cast<const float4*>(src + Ee);
            *reinterpret_cast<float4*>(&Ks[r][4 * f]) = kv;
            float4 vv = *reinterpret_cast<const float4*>(src + 2 * Ee);
            Vt[4 * f + 0][r] = vv.x;
            Vt[4 * f + 1][r] = vv.y;
            Vt[4 * f + 2][r] = vv.z;
            Vt[4 * f + 3][r] = vv.w;
        }
        __syncthreads();

        // ---- S = Q K^T : 3 k-chunks x 8 key-blocks ----
        float s[8][4];
#pragma unroll
        for (int jb = 0; jb < 8; ++jb)
#pragma unroll
            for (int r = 0; r < 4; ++r) s[jb][r] = 0.0f;
#pragma unroll
        for (int kc = 0; kc < 3; ++kc) {
            int kA = 16 * kc + 2 * tig;
#pragma unroll
            for (int jb = 0; jb < 8; ++jb) {
                const float* kr = &Ks[8 * jb + g][0];
                uint32_t b0 = packh2(kr[kA], kr[kA + 1]);
                uint32_t b1 = packh2(kr[kA + 8], kr[kA + 9]);
                mma_f16(s[jb], qf[kc][0], qf[kc][1], qf[kc][2], qf[kc][3],
                        b0, b1);
            }
        }

        // ---- online softmax (fp32, unchanged) ----
        float cm0 = -1e30f, cm1 = -1e30f;
#pragma unroll
        for (int jb = 0; jb < 8; ++jb) {
            cm0 = fmaxf(cm0, fmaxf(s[jb][0], s[jb][1]));
            cm1 = fmaxf(cm1, fmaxf(s[jb][2], s[jb][3]));
        }
        cm0 = fmaxf(cm0, __shfl_xor_sync(0xffffffffu, cm0, 1));
        cm0 = fmaxf(cm0, __shfl_xor_sync(0xffffffffu, cm0, 2));
        cm1 = fmaxf(cm1, __shfl_xor_sync(0xffffffffu, cm1, 1));
        cm1 = fmaxf(cm1, __shfl_xor_sync(0xffffffffu, cm1, 2));
        float nm0 = fmaxf(mr0, cm0), nm1 = fmaxf(mr1, cm1);
        float corr0 = __expf(mr0 - nm0), corr1 = __expf(mr1 - nm1);
        float rs0 = 0.0f, rs1 = 0.0f;
#pragma unroll
        for (int jb = 0; jb < 8; ++jb) {
            s[jb][0] = __expf(s[jb][0] - nm0);
            s[jb][1] = __expf(s[jb][1] - nm0);
            rs0 += s[jb][0] + s[jb][1];
            s[jb][2] = __expf(s[jb][2] - nm1);
            s[jb][3] = __expf(s[jb][3] - nm1);
            rs1 += s[jb][2] + s[jb][3];
        }
        rs0 += __shfl_xor_sync(0xffffffffu, rs0, 1);
        rs0 += __shfl_xor_sync(0xffffffffu, rs0, 2);
        rs1 += __shfl_xor_sync(0xffffffffu, rs1, 1);
        rs1 += __shfl_xor_sync(0xffffffffu, rs1, 2);
        l0 = l0 * corr0 + rs0;
        l1 = l1 * corr1 + rs1;
        mr0 = nm0; mr1 = nm1;
#pragma unroll
        for (int nb = 0; nb < 6; ++nb) {
            of[nb][0] *= corr0; of[nb][1] *= corr0;
            of[nb][2] *= corr1; of[nb][3] *= corr1;
        }

        // ---- write P to smem (own warp rows), then O += P V ----
#pragma unroll
        for (int jb = 0; jb < 8; ++jb) {
            *reinterpret_cast<float2*>(&QP[m0 + g][8 * jb + 2 * tig]) =
                make_float2(s[jb][0], s[jb][1]);
            *reinterpret_cast<float2*>(&QP[m0 + g + 8][8 * jb + 2 * tig]) =
                make_float2(s[jb][2], s[jb][3]);
        }
        __syncwarp();

#pragma unroll
        for (int pc = 0; pc < 4; ++pc) {
            int kA = 16 * pc + 2 * tig;
            uint32_t pa0 = packh2(QP[m0 + g][kA],     QP[m0 + g][kA + 1]);
            uint32_t pa1 = packh2(QP[m0 + g + 8][kA], QP[m0 + g + 8][kA + 1]);
            uint32_t pa2 = packh2(QP[m0 + g][kA + 8], QP[m0 + g][kA + 9]);
            uint32_t pa3 = packh2(QP[m0 + g + 8][kA + 8], QP[m0 + g + 8][kA + 9]);
#pragma unroll
            for (int nb = 0; nb < 6; ++nb) {
                const float* vr = &Vt[8 * nb + g][0];
                uint32_t b0 = packh2(vr[kA], vr[kA + 1]);
                uint32_t b1 = packh2(vr[kA + 8], vr[kA + 9]);
                mma_f16(of[nb], pa0, pa1, pa2, pa3, b0, b1);
            }
        }
        __syncthreads();
    }

    float inv0 = 1.0f / l0, inv1 = 1.0f / l1;
    float* orow0 = xt + (size_t)(b * Nn + q0 + m0 + g) * Ee + h * DH;
    float* orow1 = orow0 + (size_t)8 * Ee;
#pragma unroll
    for (int nb = 0; nb < 6; ++nb) {
        int col = 8 * nb + 2 * tig;
        *reinterpret_cast<float2*>(&orow0[col]) =
            make_float2(of[nb][0] * inv0, of[nb][1] * inv0);
        *reinterpret_cast<float2*>(&orow1[col]) =
            make_float2(of[nb][2] * inv1, of[nb][3] * inv1);
    }
}

// ---------------------------------------------------------------------------
// Spatial attention: 192 threads, thread = (head, token).
// ---------------------------------------------------------------------------
__global__ __launch_bounds__(192)
void spatial_attn(const float* __restrict__ qkv, float* __restrict__ xs)
{
    __shared__ float sh[8][3 * DH];
    const int gBlk = blockIdx.x;
    const int tid = threadIdx.x;

    const float* base = qkv + (size_t)gBlk * E3;
    for (int j = tid; j < 288; j += 192) {
        int sec = j / 96, w = j - sec * 96;
        int h = w / 12, i4 = w - h * 12;
        float4 v = *reinterpret_cast<const float4*>(
            &base[sec * Ee + h * DH + 4 * i4]);
        *reinterpret_cast<float4*>(&sh[h][sec * DH + 4 * i4]) = v;
    }
    __syncthreads();

    const int h = tid / NT, t = tid - h * NT;
    const float* q = sh[h];
    const float* k = sh[h] + DH;
    const float* v = sh[h] + 2 * DH;
    float q0 = q[t], q1 = q[NT + t];
    float s[NT];
    float mx = -1e30f;
#pragma unroll
    for (int u = 0; u < NT; ++u) {
        s[u] = fmaf(q1, k[NT + u], q0 * k[u]);
        mx = fmaxf(mx, s[u]);
    }
    float sum = 0.0f;
#pragma unroll
    for (int u = 0; u < NT; ++u) { s[u] = __expf(s[u] - mx); sum += s[u]; }
    float inv = 1.0f / sum;
    float o0 = 0.0f, o1 = 0.0f;
#pragma unroll
    for (int u = 0; u < NT; ++u) {
        o0 = fmaf(s[u], v[u], o0);
        o1 = fmaf(s[u], v[NT + u], o1);
    }
    float* op = xs + (size_t)gBlk * Ee + h * DH;
    op[t]      = o0 * inv;
    op[NT + t] = o1 * inv;
}

// ---------------------------------------------------------------------------
// Mean stage 1: partial sums over 128-frame slices. grid (B, 6, 4), block 128.
// ---------------------------------------------------------------------------
__global__ __launch_bounds__(128)
void mean_part(const float* __restrict__ xt, const float* __restrict__ xs,
               float* __restrict__ part)
{
    const int b = blockIdx.x;
    const int j = blockIdx.y * 128 + threadIdx.x;
    const int z = blockIdx.z;
    const float* src = (j < Ee)
        ? xt + (size_t)b * Nn * Ee + (size_t)(z * 128) * Ee + j
        : xs + (size_t)b * Nn * Ee + (size_t)(z * 128) * Ee + (j - Ee);
    float acc = 0.0f;
#pragma unroll 8
    for (int n = 0; n < 128; ++n) acc += src[(size_t)n * Ee];
    part[((size_t)z * Bb + b) * (2 * Ee) + j] = acc;
}

// ---------------------------------------------------------------------------
// Mean stage 2: reduce 4 partials -> alphaIn. grid (B, 6), block 128.
// ---------------------------------------------------------------------------
__global__ __launch_bounds__(128)
void mean_reduce(const float* __restrict__ part, float* __restrict__ alphaIn)
{
    const int b = blockIdx.x;
    const int j = blockIdx.y * 128 + threadIdx.x;
    float acc = 0.0f;
#pragma unroll
    for (int z = 0; z < 4; ++z)
        acc += part[((size_t)z * Bb + b) * (2 * Ee) + j];
    alphaIn[b * 2 * Ee + j] = acc * (1.0f / (float)Nn);
}

// ---------------------------------------------------------------------------
// Gating
// ---------------------------------------------------------------------------
__global__ __launch_bounds__(768)
void gate_kernel(const float* __restrict__ alphaIn, const float* __restrict__ Wts,
                 const float* __restrict__ bts,
                 float* __restrict__ g0, float* __restrict__ g1)
{
    __shared__ float a[768];
    __shared__ float val[768];
    const int b = blockIdx.x, t = threadIdx.x;
    a[t] = alphaIn[b * 768 + t];
    __syncthreads();
    float acc = bts[t];
    for (int k = 0; k < 768; ++k)
        acc = fmaf(a[k], Wts[(size_t)k * 768 + t], acc);
    val[t] = acc;
    __syncthreads();
    if (t < Ee) {
        float v0 = val[2 * t], v1 = val[2 * t + 1];
        float mx = fmaxf(v0, v1);
        float e0 = __expf(v0 - mx), e1 = __expf(v1 - mx);
        float inv = 1.0f / (e0 + e1);
        g0[b * Ee + t] = e0 * inv;
        g1[b * Ee + t] = e1 * inv;
    }
}

// ---------------------------------------------------------------------------
// Launch
// ---------------------------------------------------------------------------
extern "C" void kernel_launch(void* const* d_in, const int* in_sizes, int n_in,
                              void* d_out, int out_size)
{
    const float* x      = (const float*)d_in[0];
    const float* Wqkv_t = (const float*)d_in[1];
    const float* bqkv_t = (const float*)d_in[2];
    const float* Wqkv_s = (const float*)d_in[3];
    const float* bqkv_s = (const float*)d_in[4];
    const float* Wts    = (const float*)d_in[5];
    const float* bts    = (const float*)d_in[6];
    const float* Wfc_t  = (const float*)d_in[7];
    const float* bfc_t  = (const float*)d_in[8];
    const float* Wfc_s  = (const float*)d_in[9];
    const float* bfc_s  = (const float*)d_in[10];
    float* out = (float*)d_out;

    float *qkvT, *qkvS, *xt, *xs, *part, *alphaIn, *g0, *g1;
    cudaGetSymbolAddress((void**)&qkvT,    g_qkv_t);
    cudaGetSymbolAddress((void**)&qkvS,    g_qkv_s);
    cudaGetSymbolAddress((void**)&xt,      g_xt);
    cudaGetSymbolAddress((void**)&xs,      g_xs);
    cudaGetSymbolAddress((void**)&part,    g_alpha_part);
    cudaGetSymbolAddress((void**)&alphaIn, g_alpha_in);
    cudaGetSymbolAddress((void**)&g0,      g_gate0);
    cudaGetSymbolAddress((void**)&g1,      g_gate1);

    cudaFuncSetAttribute(mma_gemm<0>,
                         cudaFuncAttributeMaxDynamicSharedMemorySize, GEMM_SMEM);
    cudaFuncSetAttribute(mma_gemm<1>,
                         cudaFuncAttributeMaxDynamicSharedMemorySize, GEMM_SMEM);

    // Fused QKV projections (both weight sets in one launch)
    mma_gemm<0><<<dim3(18, Mrows / 128), 256, GEMM_SMEM>>>(
        x, nullptr, Wqkv_t, Wqkv_s, nullptr, nullptr, bqkv_t, bqkv_s,
        qkvT, qkvS, INd, E3);

    // Attentions
    flash_tattn<<<dim3(Nn / 64, Hh, Bb), 128>>>(qkvT, xt);
    spatial_attn<<<Mrows, 192>>>(qkvS, xs);

    // Gating (split-n mean, deterministic two-stage)
    mean_part<<<dim3(Bb, 6, 4), 128>>>(xt, xs, part);
    mean_reduce<<<dim3(Bb, 6), 128>>>(part, alphaIn);
    gate_kernel<<<Bb, 768>>>(alphaIn, Wts, bts, g0, g1);

    // Fused gated output projection
    mma_gemm<1><<<dim3(OUTd / 128, Mrows / 128), 256, GEMM_SMEM>>>(
        xt, xs, Wfc_t, Wfc_s, g0, g1, bfc_t, bfc_s,
        out, nullptr, Ee, OUTd);
}

// round 10
// speedup vs baseline: 1.9401x; 1.3660x over previous
#include <cuda_runtime.h>
#include <cuda_fp16.h>
#include <cstdint>

// ---------------------------------------------------------------------------
// Problem constants
// ---------------------------------------------------------------------------
#define Bb   32
#define Nn   512
#define NT   24
#define Hh   8
#define DH   48
#define Ee   384          // H*DH
#define INd  768          // C*NT
#define OUTd 768
#define E3   1152         // 3*E
#define Mrows (Bb*Nn)     // 16384

// ---------------------------------------------------------------------------
// Scratch (device globals)
// ---------------------------------------------------------------------------
__device__ float  g_qkv_t[(size_t)Mrows * E3];
__device__ float  g_qkv_s[(size_t)Mrows * E3];
__device__ float  g_xt[(size_t)Mrows * Ee];
__device__ float  g_xs[(size_t)Mrows * Ee];
__device__ float  g_alpha_part[4 * Bb * 2 * Ee];
__device__ float  g_alpha_in[Bb * 2 * Ee];
__device__ float  g_gate0[Bb * Ee];
__device__ float  g_gate1[Bb * Ee];
// fp16 operands
__device__ __half g_xh[(size_t)Mrows * INd];
__device__ __half g_wqT[(size_t)INd * E3];
__device__ __half g_wqS[(size_t)INd * E3];
__device__ __half g_wfT[(size_t)Ee * OUTd];
__device__ __half g_wfS[(size_t)Ee * OUTd];
__device__ __half g_xtg[(size_t)Mrows * Ee];
__device__ __half g_xsg[(size_t)Mrows * Ee];

// ---------------------------------------------------------------------------
// helpers
// ---------------------------------------------------------------------------
__device__ __forceinline__ uint32_t packh2(float lo, float hi) {
    __half2 h = __floats2half2_rn(lo, hi);
    return *reinterpret_cast<uint32_t*>(&h);
}

__device__ __forceinline__ void mma_f16(float c[4],
                                        uint32_t a0, uint32_t a1,
                                        uint32_t a2, uint32_t a3,
                                        uint32_t b0, uint32_t b1) {
    asm volatile(
        "mma.sync.aligned.m16n8k16.row.col.f32.f16.f16.f32 "
        "{%0,%1,%2,%3}, {%4,%5,%6,%7}, {%8,%9}, {%0,%1,%2,%3};\n"
        : "+f"(c[0]), "+f"(c[1]), "+f"(c[2]), "+f"(c[3])
        : "r"(a0), "r"(a1), "r"(a2), "r"(a3), "r"(b0), "r"(b1));
}

__device__ __forceinline__ void cp_async16(void* smem_dst, const void* gmem_src) {
    uint32_t d = (uint32_t)__cvta_generic_to_shared(smem_dst);
    asm volatile("cp.async.cg.shared.global [%0], [%1], 16;\n"
                 :: "r"(d), "l"(gmem_src));
}
__device__ __forceinline__ void cp_async_commit() {
    asm volatile("cp.async.commit_group;\n");
}
__device__ __forceinline__ void cp_async_wait_all() {
    asm volatile("cp.async.wait_group 0;\n");
}

__device__ __forceinline__ void ldm_x4(uint32_t* r, const void* p) {
    uint32_t a = (uint32_t)__cvta_generic_to_shared(p);
    asm volatile("ldmatrix.sync.aligned.m8n8.x4.shared.b16 {%0,%1,%2,%3}, [%4];"
                 : "=r"(r[0]), "=r"(r[1]), "=r"(r[2]), "=r"(r[3]) : "r"(a));
}
__device__ __forceinline__ void ldm_x4t(uint32_t* r, const void* p) {
    uint32_t a = (uint32_t)__cvta_generic_to_shared(p);
    asm volatile("ldmatrix.sync.aligned.m8n8.x4.trans.shared.b16 {%0,%1,%2,%3}, [%4];"
                 : "=r"(r[0]), "=r"(r[1]), "=r"(r[2]), "=r"(r[3]) : "r"(a));
}

// ---------------------------------------------------------------------------
// fp32 -> fp16 convert (n4 float4 groups, exact grid cover)
// ---------------------------------------------------------------------------
__global__ __launch_bounds__(256)
void f2h(const float* __restrict__ in, __half* __restrict__ out)
{
    const int i4 = blockIdx.x * 256 + threadIdx.x;
    float4 v = reinterpret_cast<const float4*>(in)[i4];
    uint2 o;
    o.x = packh2(v.x, v.y);
    o.y = packh2(v.z, v.w);
    reinterpret_cast<uint2*>(out)[i4] = o;
}

// ---------------------------------------------------------------------------
// Gated premultiply to fp16: xtg = half(xt*g0[b]), xsg = half(xs*g1[b])
// grid 6144 x 256, float4 groups (exact cover of Mrows*Ee/4)
// ---------------------------------------------------------------------------
__global__ __launch_bounds__(256)
void gated_premul_h(const float* __restrict__ xt, const float* __restrict__ xs,
                    const float* __restrict__ g0, const float* __restrict__ g1,
                    __half* __restrict__ xtg, __half* __restrict__ xsg)
{
    const int i4 = blockIdx.x * 256 + threadIdx.x;
    const int row = i4 / 96;            // Ee/4 = 96
    const int k4 = i4 - row * 96;
    const int b = row >> 9;
    float4 gv0 = reinterpret_cast<const float4*>(g0 + b * Ee)[k4];
    float4 gv1 = reinterpret_cast<const float4*>(g1 + b * Ee)[k4];
    float4 a = reinterpret_cast<const float4*>(xt)[i4];
    uint2 o;
    o.x = packh2(a.x * gv0.x, a.y * gv0.y);
    o.y = packh2(a.z * gv0.z, a.w * gv0.w);
    reinterpret_cast<uint2*>(xtg)[i4] = o;
    float4 s = reinterpret_cast<const float4*>(xs)[i4];
    uint2 p;
    p.x = packh2(s.x * gv1.x, s.y * gv1.y);
    p.y = packh2(s.z * gv1.z, s.w * gv1.w);
    reinterpret_cast<uint2*>(xsg)[i4] = p;
}

// ---------------------------------------------------------------------------
// fp16 GEMM, 128x128 tile, BK=32, 256 threads, double buffered cp.async,
// fp16 smem tiles + ldmatrix fragment loads.
//   A tile [128][40] halves (80B stride: ldmatrix conflict-free)
//   B tile [32][136] halves (272B stride: ldmatrix conflict-free)
// MODE 0 (dual-N QKV): bx<9 -> C0 = A @ W0 + bias0 ; bx>=9 -> C1 = A @ W1 + bias1
// MODE 1 (fused out):  C = A0 @ W0 + A1 @ W1 + bias0 + bias1   (A pre-gated)
// ---------------------------------------------------------------------------
template <int MODE>
__global__ __launch_bounds__(256, 2)
void mma_gemm_h(const __half* __restrict__ A0, const __half* __restrict__ A1,
                const __half* __restrict__ W0, const __half* __restrict__ W1,
                const float* __restrict__ bias0, const float* __restrict__ bias1,
                float* __restrict__ C0, float* __restrict__ C1,
                int Kd, int Nd)
{
    extern __shared__ __half hsm[];
    __half (*As)[128][40] = reinterpret_cast<__half(*)[128][40]>(hsm);
    __half (*Bs)[32][136] = reinterpret_cast<__half(*)[32][136]>(hsm + 2 * 128 * 40);

    const int tid  = threadIdx.x;
    const int lane = tid & 31;
    const int warp = tid >> 5;
    const int g    = lane >> 2;
    const int tig  = lane & 3;
    const int warpM = (warp & 1) * 64;
    const int warpN = (warp >> 1) * 32;

    const int rowBase = blockIdx.y * 128;

    int colBase, half_;
    const __half* Wsel;
    const float* biasSel;
    float* Csel;
    if (MODE == 0) {
        half_ = (blockIdx.x >= 9);
        colBase = (blockIdx.x - half_ * 9) * 128;
        Wsel = half_ ? W1 : W0;
        biasSel = half_ ? bias1 : bias0;
        Csel = half_ ? C1 : C0;
    } else {
        colBase = blockIdx.x * 128;
        Wsel = nullptr; biasSel = nullptr; Csel = C0;
    }

    const int perPass = Kd >> 5;
    const int nChunks = (MODE == 1) ? 2 * perPass : perPass;

    auto issueLoad = [&](int c, int buf) {
        int pass = (MODE == 1) ? (c / perPass) : 0;
        int k0 = ((MODE == 1) ? (c - pass * perPass) : c) << 5;
        const __half* A = (MODE == 1 && pass) ? A1 : A0;
        const __half* W = (MODE == 0) ? Wsel : (pass ? W1 : W0);
        // A tile: 128 rows x 32 halves = 512 x 16B chunks
#pragma unroll
        for (int i = 0; i < 2; ++i) {
            int idx = i * 256 + tid;
            int r = idx >> 2, c8 = (idx & 3) * 8;
            cp_async16(&As[buf][r][c8],
                       &A[(size_t)(rowBase + r) * Kd + k0 + c8]);
        }
        // B tile: 32 rows x 128 halves = 512 x 16B chunks
#pragma unroll
        for (int i = 0; i < 2; ++i) {
            int idx = i * 256 + tid;
            int r = idx >> 4, c8 = (idx & 15) * 8;
            cp_async16(&Bs[buf][r][c8],
                       &W[(size_t)(k0 + r) * Nd + colBase + c8]);
        }
        cp_async_commit();
    };

    float acc[4][4][4];
#pragma unroll
    for (int i = 0; i < 4; ++i)
#pragma unroll
        for (int j = 0; j < 4; ++j)
#pragma unroll
            for (int r = 0; r < 4; ++r) acc[i][j][r] = 0.0f;

    issueLoad(0, 0);

    const int aRowL = lane & 15;           // ldmatrix source row within 16
    const int aColH = (lane >> 4) << 3;    // +8 for upper half-lanes

    for (int c = 0; c < nChunks; ++c) {
        const int buf = c & 1;
        cp_async_wait_all();
        __syncthreads();
        if (c + 1 < nChunks) issueLoad(c + 1, buf ^ 1);

#pragma unroll
        for (int kk = 0; kk < 32; kk += 16) {
            uint32_t af[4][4];
#pragma unroll
            for (int i = 0; i < 4; ++i)
                ldm_x4(af[i], &As[buf][warpM + 16 * i + aRowL][kk + aColH]);
            uint32_t bf[4][2];
#pragma unroll
            for (int j2 = 0; j2 < 2; ++j2) {
                uint32_t t[4];
                ldm_x4t(t, &Bs[buf][kk + aRowL][warpN + 16 * j2 + aColH]);
                bf[2 * j2][0] = t[0]; bf[2 * j2][1] = t[1];
                bf[2 * j2 + 1][0] = t[2]; bf[2 * j2 + 1][1] = t[3];
            }
#pragma unroll
            for (int i = 0; i < 4; ++i)
#pragma unroll
                for (int j = 0; j < 4; ++j)
                    mma_f16(acc[i][j], af[i][0], af[i][1], af[i][2],
                            af[i][3], bf[j][0], bf[j][1]);
        }
    }
    __syncthreads();

    // ---- epilogue ----
#pragma unroll
    for (int i = 0; i < 4; ++i) {
#pragma unroll
        for (int j = 0; j < 4; ++j) {
            int col = colBase + warpN + 8 * j + 2 * tig;
            float bsum0, bsum1;
            if (MODE == 1) {
                bsum0 = bias0[col] + bias1[col];
                bsum1 = bias0[col + 1] + bias1[col + 1];
            } else {
                bsum0 = biasSel[col];
                bsum1 = biasSel[col + 1];
            }
            int row0 = rowBase + warpM + 16 * i + g;
            float* Cw = (MODE == 0) ? Csel : C0;
            float2 o0 = make_float2(acc[i][j][0] + bsum0, acc[i][j][1] + bsum1);
            *reinterpret_cast<float2*>(&Cw[(size_t)row0 * Nd + col]) = o0;
            float2 o1 = make_float2(acc[i][j][2] + bsum0, acc[i][j][3] + bsum1);
            *reinterpret_cast<float2*>(&Cw[(size_t)(row0 + 8) * Nd + col]) = o1;
        }
    }
}

#define GEMM_SMEM (2 * 128 * 40 * 2 + 2 * 32 * 136 * 2)

// ---------------------------------------------------------------------------
// Flash temporal attention, fp16 m16n8k16 (unchanged from R9, passing)
// ---------------------------------------------------------------------------
__global__ __launch_bounds__(128)
void flash_tattn(const float* __restrict__ qkv, float* __restrict__ xt)
{
    __shared__ float QP[64][68];
    __shared__ float Ks[64][52];
    __shared__ float Vt[48][68];

    const int b = blockIdx.z, h = blockIdx.y;
    const int q0 = blockIdx.x * 64;
    const int tid = threadIdx.x;
    const int warp = tid >> 5, lane = tid & 31;
    const int g = lane >> 2, tig = lane & 3;
    const int m0 = warp * 16;
    const float scale = 0.14433756729740643f;

    const float* base = qkv + (size_t)(b * Nn) * E3 + h * DH;

    for (int i = tid; i < 64 * 12; i += 128) {
        int r = i / 12, f = i % 12;
        float4 v = *reinterpret_cast<const float4*>(
            &base[(size_t)(q0 + r) * E3 + 4 * f]);
        v.x *= scale; v.y *= scale; v.z *= scale; v.w *= scale;
        *reinterpret_cast<float4*>(&QP[r][4 * f]) = v;
    }
    __syncthreads();

    uint32_t qf[3][4];
#pragma unroll
    for (int kc = 0; kc < 3; ++kc) {
        int kA = 16 * kc + 2 * tig;
        qf[kc][0] = packh2(QP[m0 + g][kA],     QP[m0 + g][kA + 1]);
        qf[kc][1] = packh2(QP[m0 + g + 8][kA], QP[m0 + g + 8][kA + 1]);
        qf[kc][2] = packh2(QP[m0 + g][kA + 8], QP[m0 + g][kA + 9]);
        qf[kc][3] = packh2(QP[m0 + g + 8][kA + 8], QP[m0 + g + 8][kA + 9]);
    }
    __syncthreads();

    float of[6][4];
#pragma unroll
    for (int nb = 0; nb < 6; ++nb)
#pragma unroll
        for (int r = 0; r < 4; ++r) of[nb][r] = 0.0f;
    float mr0 = -1e30f, mr1 = -1e30f, l0 = 0.0f, l1 = 0.0f;

    for (int c0 = 0; c0 < Nn; c0 += 64) {
        for (int i = tid; i < 64 * 12; i += 128) {
            int r = i / 12, f = i % 12;
            const float* src = &base[(size_t)(c0 + r) * E3 + 4 * f];
            float4 kv = *reinterpret_cast<const float4*>(src + Ee);
            *reinterpret_cast<float4*>(&Ks[r][4 * f]) = kv;
            float4 vv = *reinterpret_cast<const float4*>(src + 2 * Ee);
            Vt[4 * f + 0][r] = vv.x;
            Vt[4 * f + 1][r] = vv.y;
            Vt[4 * f + 2][r] = vv.z;
            Vt[4 * f + 3][r] = vv.w;
        }
        __syncthreads();

        float s[8][4];
#pragma unroll
        for (int jb = 0; jb < 8; ++jb)
#pragma unroll
            for (int r = 0; r < 4; ++r) s[jb][r] = 0.0f;
#pragma unroll
        for (int kc = 0; kc < 3; ++kc) {
            int kA = 16 * kc + 2 * tig;
#pragma unroll
            for (int jb = 0; jb < 8; ++jb) {
                const float* kr = &Ks[8 * jb + g][0];
                uint32_t b0 = packh2(kr[kA], kr[kA + 1]);
                uint32_t b1 = packh2(kr[kA + 8], kr[kA + 9]);
                mma_f16(s[jb], qf[kc][0], qf[kc][1], qf[kc][2], qf[kc][3],
                        b0, b1);
            }
        }

        float cm0 = -1e30f, cm1 = -1e30f;
#pragma unroll
        for (int jb = 0; jb < 8; ++jb) {
            cm0 = fmaxf(cm0, fmaxf(s[jb][0], s[jb][1]));
            cm1 = fmaxf(cm1, fmaxf(s[jb][2], s[jb][3]));
        }
        cm0 = fmaxf(cm0, __shfl_xor_sync(0xffffffffu, cm0, 1));
        cm0 = fmaxf(cm0, __shfl_xor_sync(0xffffffffu, cm0, 2));
        cm1 = fmaxf(cm1, __shfl_xor_sync(0xffffffffu, cm1, 1));
        cm1 = fmaxf(cm1, __shfl_xor_sync(0xffffffffu, cm1, 2));
        float nm0 = fmaxf(mr0, cm0), nm1 = fmaxf(mr1, cm1);
        float corr0 = __expf(mr0 - nm0), corr1 = __expf(mr1 - nm1);
        float rs0 = 0.0f, rs1 = 0.0f;
#pragma unroll
        for (int jb = 0; jb < 8; ++jb) {
            s[jb][0] = __expf(s[jb][0] - nm0);
            s[jb][1] = __expf(s[jb][1] - nm0);
            rs0 += s[jb][0] + s[jb][1];
            s[jb][2] = __expf(s[jb][2] - nm1);
            s[jb][3] = __expf(s[jb][3] - nm1);
            rs1 += s[jb][2] + s[jb][3];
        }
        rs0 += __shfl_xor_sync(0xffffffffu, rs0, 1);
        rs0 += __shfl_xor_sync(0xffffffffu, rs0, 2);
        rs1 += __shfl_xor_sync(0xffffffffu, rs1, 1);
        rs1 += __shfl_xor_sync(0xffffffffu, rs1, 2);
        l0 = l0 * corr0 + rs0;
        l1 = l1 * corr1 + rs1;
        mr0 = nm0; mr1 = nm1;
#pragma unroll
        for (int nb = 0; nb < 6; ++nb) {
            of[nb][0] *= corr0; of[nb][1] *= corr0;
            of[nb][2] *= corr1; of[nb][3] *= corr1;
        }

#pragma unroll
        for (int jb = 0; jb < 8; ++jb) {
            *reinterpret_cast<float2*>(&QP[m0 + g][8 * jb + 2 * tig]) =
                make_float2(s[jb][0], s[jb][1]);
            *reinterpret_cast<float2*>(&QP[m0 + g + 8][8 * jb + 2 * tig]) =
                make_float2(s[jb][2], s[jb][3]);
        }
        __syncwarp();

#pragma unroll
        for (int pc = 0; pc < 4; ++pc) {
            int kA = 16 * pc + 2 * tig;
            uint32_t pa0 = packh2(QP[m0 + g][kA],     QP[m0 + g][kA + 1]);
            uint32_t pa1 = packh2(QP[m0 + g + 8][kA], QP[m0 + g + 8][kA + 1]);
            uint32_t pa2 = packh2(QP[m0 + g][kA + 8], QP[m0 + g][kA + 9]);
            uint32_t pa3 = packh2(QP[m0 + g + 8][kA + 8], QP[m0 + g + 8][kA + 9]);
#pragma unroll
            for (int nb = 0; nb < 6; ++nb) {
                const float* vr = &Vt[8 * nb + g][0];
                uint32_t b0 = packh2(vr[kA], vr[kA + 1]);
                uint32_t b1 = packh2(vr[kA + 8], vr[kA + 9]);
                mma_f16(of[nb], pa0, pa1, pa2, pa3, b0, b1);
            }
        }
        __syncthreads();
    }

    float inv0 = 1.0f / l0, inv1 = 1.0f / l1;
    float* orow0 = xt + (size_t)(b * Nn + q0 + m0 + g) * Ee + h * DH;
    float* orow1 = orow0 + (size_t)8 * Ee;
#pragma unroll
    for (int nb = 0; nb < 6; ++nb) {
        int col = 8 * nb + 2 * tig;
        *reinterpret_cast<float2*>(&orow0[col]) =
            make_float2(of[nb][0] * inv0, of[nb][1] * inv0);
        *reinterpret_cast<float2*>(&orow1[col]) =
            make_float2(of[nb][2] * inv1, of[nb][3] * inv1);
    }
}

// ---------------------------------------------------------------------------
// Spatial attention: 192 threads, thread = (head, token).
// ---------------------------------------------------------------------------
__global__ __launch_bounds__(192)
void spatial_attn(const float* __restrict__ qkv, float* __restrict__ xs)
{
    __shared__ float sh[8][3 * DH];
    const int gBlk = blockIdx.x;
    const int tid = threadIdx.x;

    const float* base = qkv + (size_t)gBlk * E3;
    for (int j = tid; j < 288; j += 192) {
        int sec = j / 96, w = j - sec * 96;
        int h = w / 12, i4 = w - h * 12;
        float4 v = *reinterpret_cast<const float4*>(
            &base[sec * Ee + h * DH + 4 * i4]);
        *reinterpret_cast<float4*>(&sh[h][sec * DH + 4 * i4]) = v;
    }
    __syncthreads();

    const int h = tid / NT, t = tid - h * NT;
    const float* q = sh[h];
    const float* k = sh[h] + DH;
    const float* v = sh[h] + 2 * DH;
    float q0 = q[t], q1 = q[NT + t];
    float s[NT];
    float mx = -1e30f;
#pragma unroll
    for (int u = 0; u < NT; ++u) {
        s[u] = fmaf(q1, k[NT + u], q0 * k[u]);
        mx = fmaxf(mx, s[u]);
    }
    float sum = 0.0f;
#pragma unroll
    for (int u = 0; u < NT; ++u) { s[u] = __expf(s[u] - mx); sum += s[u]; }
    float inv = 1.0f / sum;
    float o0 = 0.0f, o1 = 0.0f;
#pragma unroll
    for (int u = 0; u < NT; ++u) {
        o0 = fmaf(s[u], v[u], o0);
        o1 = fmaf(s[u], v[NT + u], o1);
    }
    float* op = xs + (size_t)gBlk * Ee + h * DH;
    op[t]      = o0 * inv;
    op[NT + t] = o1 * inv;
}

// ---------------------------------------------------------------------------
// Mean stage 1 + 2 (unchanged)
// ---------------------------------------------------------------------------
__global__ __launch_bounds__(128)
void mean_part(const float* __restrict__ xt, const float* __restrict__ xs,
               float* __restrict__ part)
{
    const int b = blockIdx.x;
    const int j = blockIdx.y * 128 + threadIdx.x;
    const int z = blockIdx.z;
    const float* src = (j < Ee)
        ? xt + (size_t)b * Nn * Ee + (size_t)(z * 128) * Ee + j
        : xs + (size_t)b * Nn * Ee + (size_t)(z * 128) * Ee + (j - Ee);
    float acc = 0.0f;
#pragma unroll 8
    for (int n = 0; n < 128; ++n) acc += src[(size_t)n * Ee];
    part[((size_t)z * Bb + b) * (2 * Ee) + j] = acc;
}

__global__ __launch_bounds__(128)
void mean_reduce(const float* __restrict__ part, float* __restrict__ alphaIn)
{
    const int b = blockIdx.x;
    const int j = blockIdx.y * 128 + threadIdx.x;
    float acc = 0.0f;
#pragma unroll
    for (int z = 0; z < 4; ++z)
        acc += part[((size_t)z * Bb + b) * (2 * Ee) + j];
    alphaIn[b * 2 * Ee + j] = acc * (1.0f / (float)Nn);
}

// ---------------------------------------------------------------------------
// Gating (unchanged)
// ---------------------------------------------------------------------------
__global__ __launch_bounds__(768)
void gate_kernel(const float* __restrict__ alphaIn, const float* __restrict__ Wts,
                 const float* __restrict__ bts,
                 float* __restrict__ g0, float* __restrict__ g1)
{
    __shared__ float a[768];
    __shared__ float val[768];
    const int b = blockIdx.x, t = threadIdx.x;
    a[t] = alphaIn[b * 768 + t];
    __syncthreads();
    float acc = bts[t];
    for (int k = 0; k < 768; ++k)
        acc = fmaf(a[k], Wts[(size_t)k * 768 + t], acc);
    val[t] = acc;
    __syncthreads();
    if (t < Ee) {
        float v0 = val[2 * t], v1 = val[2 * t + 1];
        float mx = fmaxf(v0, v1);
        float e0 = __expf(v0 - mx), e1 = __expf(v1 - mx);
        float inv = 1.0f / (e0 + e1);
        g0[b * Ee + t] = e0 * inv;
        g1[b * Ee + t] = e1 * inv;
    }
}

// ---------------------------------------------------------------------------
// Launch
// ---------------------------------------------------------------------------
extern "C" void kernel_launch(void* const* d_in, const int* in_sizes, int n_in,
                              void* d_out, int out_size)
{
    const float* x      = (const float*)d_in[0];
    const float* Wqkv_t = (const float*)d_in[1];
    const float* bqkv_t = (const float*)d_in[2];
    const float* Wqkv_s = (const float*)d_in[3];
    const float* bqkv_s = (const float*)d_in[4];
    const float* Wts    = (const float*)d_in[5];
    const float* bts    = (const float*)d_in[6];
    const float* Wfc_t  = (const float*)d_in[7];
    const float* bfc_t  = (const float*)d_in[8];
    const float* Wfc_s  = (const float*)d_in[9];
    const float* bfc_s  = (const float*)d_in[10];
    float* out = (float*)d_out;

    float *qkvT, *qkvS, *xt, *xs, *part, *alphaIn, *g0, *g1;
    __half *xh, *wqT, *wqS, *wfT, *wfS, *xtg, *xsg;
    cudaGetSymbolAddress((void**)&qkvT,    g_qkv_t);
    cudaGetSymbolAddress((void**)&qkvS,    g_qkv_s);
    cudaGetSymbolAddress((void**)&xt,      g_xt);
    cudaGetSymbolAddress((void**)&xs,      g_xs);
    cudaGetSymbolAddress((void**)&part,    g_alpha_part);
    cudaGetSymbolAddress((void**)&alphaIn, g_alpha_in);
    cudaGetSymbolAddress((void**)&g0,      g_gate0);
    cudaGetSymbolAddress((void**)&g1,      g_gate1);
    cudaGetSymbolAddress((void**)&xh,      g_xh);
    cudaGetSymbolAddress((void**)&wqT,     g_wqT);
    cudaGetSymbolAddress((void**)&wqS,     g_wqS);
    cudaGetSymbolAddress((void**)&wfT,     g_wfT);
    cudaGetSymbolAddress((void**)&wfS,     g_wfS);
    cudaGetSymbolAddress((void**)&xtg,     g_xtg);
    cudaGetSymbolAddress((void**)&xsg,     g_xsg);

    // fp32 -> fp16 conversions (exact grid covers)
    f2h<<<Mrows * INd / 1024, 256>>>(x, xh);          // 12288 blocks
    f2h<<<INd * E3 / 1024, 256>>>(Wqkv_t, wqT);       // 864
    f2h<<<INd * E3 / 1024, 256>>>(Wqkv_s, wqS);       // 864
    f2h<<<Ee * OUTd / 1024, 256>>>(Wfc_t, wfT);       // 288
    f2h<<<Ee * OUTd / 1024, 256>>>(Wfc_s, wfS);       // 288

    // Fused QKV projections (fp16 operands, ldmatrix path)
    mma_gemm_h<0><<<dim3(18, Mrows / 128), 256, GEMM_SMEM>>>(
        xh, nullptr, wqT, wqS, bqkv_t, bqkv_s, qkvT, qkvS, INd, E3);

    // Attentions
    flash_tattn<<<dim3(Nn / 64, Hh, Bb), 128>>>(qkvT, xt);
    spatial_attn<<<Mrows, 192>>>(qkvS, xs);

    // Gating
    mean_part<<<dim3(Bb, 6, 4), 128>>>(xt, xs, part);
    mean_reduce<<<dim3(Bb, 6), 128>>>(part, alphaIn);
    gate_kernel<<<Bb, 768>>>(alphaIn, Wts, bts, g0, g1);

    // Pre-gated fp16 activations, then fused output projection
    gated_premul_h<<<Mrows * Ee / 1024, 256>>>(xt, xs, g0, g1, xtg, xsg);
    mma_gemm_h<1><<<dim3(OUTd / 128, Mrows / 128), 256, GEMM_SMEM>>>(
        xtg, xsg, wfT, wfS, bfc_t, bfc_s, out, nullptr, Ee, OUTd);
}

// round 11
// speedup vs baseline: 2.6092x; 1.3449x over previous
#include <cuda_runtime.h>
#include <cuda_fp16.h>
#include <cstdint>

// ---------------------------------------------------------------------------
// Problem constants
// ---------------------------------------------------------------------------
#define Bb   32
#define Nn   512
#define NT   24
#define Hh   8
#define DH   48
#define Ee   384          // H*DH
#define INd  768          // C*NT
#define OUTd 768
#define E3   1152         // 3*E
#define Mrows (Bb*Nn)     // 16384

// ---------------------------------------------------------------------------
// Scratch (device globals)
// ---------------------------------------------------------------------------
__device__ __half g_qkvTh[(size_t)Mrows * E3];   // fp16 temporal QKV
__device__ float  g_qkv_s[(size_t)Mrows * E3];
__device__ float  g_xt[(size_t)Mrows * Ee];
__device__ float  g_xs[(size_t)Mrows * Ee];
__device__ float  g_alpha_part[4 * Bb * 2 * Ee];
__device__ float  g_alpha_in[Bb * 2 * Ee];
__device__ float  g_gate0[Bb * Ee];
__device__ float  g_gate1[Bb * Ee];
// fp16 operands
__device__ __half g_xh[(size_t)Mrows * INd];
__device__ __half g_wqT[(size_t)INd * E3];
__device__ __half g_wqS[(size_t)INd * E3];
__device__ __half g_wfT[(size_t)Ee * OUTd];
__device__ __half g_wfS[(size_t)Ee * OUTd];
__device__ __half g_xtg[(size_t)Mrows * Ee];
__device__ __half g_xsg[(size_t)Mrows * Ee];

// ---------------------------------------------------------------------------
// helpers
// ---------------------------------------------------------------------------
__device__ __forceinline__ uint32_t packh2(float lo, float hi) {
    __half2 h = __floats2half2_rn(lo, hi);
    return *reinterpret_cast<uint32_t*>(&h);
}

__device__ __forceinline__ void mma_f16(float c[4],
                                        uint32_t a0, uint32_t a1,
                                        uint32_t a2, uint32_t a3,
                                        uint32_t b0, uint32_t b1) {
    asm volatile(
        "mma.sync.aligned.m16n8k16.row.col.f32.f16.f16.f32 "
        "{%0,%1,%2,%3}, {%4,%5,%6,%7}, {%8,%9}, {%0,%1,%2,%3};\n"
        : "+f"(c[0]), "+f"(c[1]), "+f"(c[2]), "+f"(c[3])
        : "r"(a0), "r"(a1), "r"(a2), "r"(a3), "r"(b0), "r"(b1));
}

__device__ __forceinline__ void cp_async16(void* smem_dst, const void* gmem_src) {
    uint32_t d = (uint32_t)__cvta_generic_to_shared(smem_dst);
    asm volatile("cp.async.cg.shared.global [%0], [%1], 16;\n"
                 :: "r"(d), "l"(gmem_src));
}
__device__ __forceinline__ void cp_async_commit() {
    asm volatile("cp.async.commit_group;\n");
}
__device__ __forceinline__ void cp_async_wait_all() {
    asm volatile("cp.async.wait_group 0;\n");
}

__device__ __forceinline__ void ldm_x4(uint32_t* r, const void* p) {
    uint32_t a = (uint32_t)__cvta_generic_to_shared(p);
    asm volatile("ldmatrix.sync.aligned.m8n8.x4.shared.b16 {%0,%1,%2,%3}, [%4];"
                 : "=r"(r[0]), "=r"(r[1]), "=r"(r[2]), "=r"(r[3]) : "r"(a));
}
__device__ __forceinline__ void ldm_x4t(uint32_t* r, const void* p) {
    uint32_t a = (uint32_t)__cvta_generic_to_shared(p);
    asm volatile("ldmatrix.sync.aligned.m8n8.x4.trans.shared.b16 {%0,%1,%2,%3}, [%4];"
                 : "=r"(r[0]), "=r"(r[1]), "=r"(r[2]), "=r"(r[3]) : "r"(a));
}

// ---------------------------------------------------------------------------
// fp32 -> fp16 convert
// ---------------------------------------------------------------------------
__global__ __launch_bounds__(256)
void f2h(const float* __restrict__ in, __half* __restrict__ out)
{
    const int i4 = blockIdx.x * 256 + threadIdx.x;
    float4 v = reinterpret_cast<const float4*>(in)[i4];
    uint2 o;
    o.x = packh2(v.x, v.y);
    o.y = packh2(v.z, v.w);
    reinterpret_cast<uint2*>(out)[i4] = o;
}

// ---------------------------------------------------------------------------
// Gated premultiply to fp16
// ---------------------------------------------------------------------------
__global__ __launch_bounds__(256)
void gated_premul_h(const float* __restrict__ xt, const float* __restrict__ xs,
                    const float* __restrict__ g0, const float* __restrict__ g1,
                    __half* __restrict__ xtg, __half* __restrict__ xsg)
{
    const int i4 = blockIdx.x * 256 + threadIdx.x;
    const int row = i4 / 96;
    const int k4 = i4 - row * 96;
    const int b = row >> 9;
    float4 gv0 = reinterpret_cast<const float4*>(g0 + b * Ee)[k4];
    float4 gv1 = reinterpret_cast<const float4*>(g1 + b * Ee)[k4];
    float4 a = reinterpret_cast<const float4*>(xt)[i4];
    uint2 o;
    o.x = packh2(a.x * gv0.x, a.y * gv0.y);
    o.y = packh2(a.z * gv0.z, a.w * gv0.w);
    reinterpret_cast<uint2*>(xtg)[i4] = o;
    float4 s = reinterpret_cast<const float4*>(xs)[i4];
    uint2 p;
    p.x = packh2(s.x * gv1.x, s.y * gv1.y);
    p.y = packh2(s.z * gv1.z, s.w * gv1.w);
    reinterpret_cast<uint2*>(xsg)[i4] = p;
}

// ---------------------------------------------------------------------------
// fp16 GEMM, 128x128 tile, BK=32, 256 threads, double buffered cp.async,
// fp16 smem tiles + ldmatrix.
// MODE 0: bx<9 -> C0h (HALF out) = A @ W0 + bias0 ; bx>=9 -> C1 (float) = A @ W1 + bias1
// MODE 1: Cf = A0 @ W0 + A1 @ W1 + bias0 + bias1   (A pre-gated fp16)
// ---------------------------------------------------------------------------
template <int MODE>
__global__ __launch_bounds__(256, 2)
void mma_gemm_h(const __half* __restrict__ A0, const __half* __restrict__ A1,
                const __half* __restrict__ W0, const __half* __restrict__ W1,
                const float* __restrict__ bias0, const float* __restrict__ bias1,
                __half* __restrict__ C0h, float* __restrict__ C1,
                float* __restrict__ Cf, int Kd, int Nd)
{
    extern __shared__ __half hsm[];
    __half (*As)[128][40] = reinterpret_cast<__half(*)[128][40]>(hsm);
    __half (*Bs)[32][136] = reinterpret_cast<__half(*)[32][136]>(hsm + 2 * 128 * 40);

    const int tid  = threadIdx.x;
    const int lane = tid & 31;
    const int warp = tid >> 5;
    const int g    = lane >> 2;
    const int tig  = lane & 3;
    const int warpM = (warp & 1) * 64;
    const int warpN = (warp >> 1) * 32;

    const int rowBase = blockIdx.y * 128;

    int colBase, half_ = 0;
    const __half* Wsel = nullptr;
    const float* biasSel = nullptr;
    if (MODE == 0) {
        half_ = (blockIdx.x >= 9);
        colBase = (blockIdx.x - half_ * 9) * 128;
        Wsel = half_ ? W1 : W0;
        biasSel = half_ ? bias1 : bias0;
    } else {
        colBase = blockIdx.x * 128;
    }

    const int perPass = Kd >> 5;
    const int nChunks = (MODE == 1) ? 2 * perPass : perPass;

    auto issueLoad = [&](int c, int buf) {
        int pass = (MODE == 1) ? (c / perPass) : 0;
        int k0 = ((MODE == 1) ? (c - pass * perPass) : c) << 5;
        const __half* A = (MODE == 1 && pass) ? A1 : A0;
        const __half* W = (MODE == 0) ? Wsel : (pass ? W1 : W0);
#pragma unroll
        for (int i = 0; i < 2; ++i) {
            int idx = i * 256 + tid;
            int r = idx >> 2, c8 = (idx & 3) * 8;
            cp_async16(&As[buf][r][c8],
                       &A[(size_t)(rowBase + r) * Kd + k0 + c8]);
        }
#pragma unroll
        for (int i = 0; i < 2; ++i) {
            int idx = i * 256 + tid;
            int r = idx >> 4, c8 = (idx & 15) * 8;
            cp_async16(&Bs[buf][r][c8],
                       &W[(size_t)(k0 + r) * Nd + colBase + c8]);
        }
        cp_async_commit();
    };

    float acc[4][4][4];
#pragma unroll
    for (int i = 0; i < 4; ++i)
#pragma unroll
        for (int j = 0; j < 4; ++j)
#pragma unroll
            for (int r = 0; r < 4; ++r) acc[i][j][r] = 0.0f;

    issueLoad(0, 0);

    const int aRowL = lane & 15;
    const int aColH = (lane >> 4) << 3;

    for (int c = 0; c < nChunks; ++c) {
        const int buf = c & 1;
        cp_async_wait_all();
        __syncthreads();
        if (c + 1 < nChunks) issueLoad(c + 1, buf ^ 1);

#pragma unroll
        for (int kk = 0; kk < 32; kk += 16) {
            uint32_t af[4][4];
#pragma unroll
            for (int i = 0; i < 4; ++i)
                ldm_x4(af[i], &As[buf][warpM + 16 * i + aRowL][kk + aColH]);
            uint32_t bf[4][2];
#pragma unroll
            for (int j2 = 0; j2 < 2; ++j2) {
                uint32_t t[4];
                ldm_x4t(t, &Bs[buf][kk + aRowL][warpN + 16 * j2 + aColH]);
                bf[2 * j2][0] = t[0]; bf[2 * j2][1] = t[1];
                bf[2 * j2 + 1][0] = t[2]; bf[2 * j2 + 1][1] = t[3];
            }
#pragma unroll
            for (int i = 0; i < 4; ++i)
#pragma unroll
                for (int j = 0; j < 4; ++j)
                    mma_f16(acc[i][j], af[i][0], af[i][1], af[i][2],
                            af[i][3], bf[j][0], bf[j][1]);
        }
    }
    __syncthreads();

    // ---- epilogue ----
#pragma unroll
    for (int i = 0; i < 4; ++i) {
#pragma unroll
        for (int j = 0; j < 4; ++j) {
            int col = colBase + warpN + 8 * j + 2 * tig;
            float bsum0, bsum1;
            if (MODE == 1) {
                bsum0 = bias0[col] + bias1[col];
                bsum1 = bias0[col + 1] + bias1[col + 1];
            } else {
                bsum0 = biasSel[col];
                bsum1 = biasSel[col + 1];
            }
            int row0 = rowBase + warpM + 16 * i + g;
            float v00 = acc[i][j][0] + bsum0, v01 = acc[i][j][1] + bsum1;
            float v10 = acc[i][j][2] + bsum0, v11 = acc[i][j][3] + bsum1;
            if (MODE == 0 && half_ == 0) {
                // fp16 output (temporal QKV)
                *reinterpret_cast<__half2*>(&C0h[(size_t)row0 * Nd + col]) =
                    __floats2half2_rn(v00, v01);
                *reinterpret_cast<__half2*>(&C0h[(size_t)(row0 + 8) * Nd + col]) =
                    __floats2half2_rn(v10, v11);
            } else {
                float* Cw = (MODE == 0) ? C1 : Cf;
                *reinterpret_cast<float2*>(&Cw[(size_t)row0 * Nd + col]) =
                    make_float2(v00, v01);
                *reinterpret_cast<float2*>(&Cw[(size_t)(row0 + 8) * Nd + col]) =
                    make_float2(v10, v11);
            }
        }
    }
}

#define GEMM_SMEM (2 * 128 * 40 * 2 + 2 * 32 * 136 * 2)

// ---------------------------------------------------------------------------
// Flash temporal attention, fp16 ldmatrix path.
// qkv in fp16; scale folded into fp32 S. CTA = (64 q, head, batch), 4 warps.
//   Qh/Ks/Vs: [64][56] halves (112B stride, ldmatrix conflict-free)
//   Ph:       [64][72] halves (144B stride, conflict-free)
// K/V double buffered via cp.async.
// ---------------------------------------------------------------------------
__global__ __launch_bounds__(128)
void flash_tattn_h(const __half* __restrict__ qkv, float* __restrict__ xt)
{
    __shared__ __half Qh[64][56];
    __shared__ __half Ks[2][64][56];
    __shared__ __half Vs[2][64][56];
    __shared__ __half Ph[64][72];

    const int b = blockIdx.z, h = blockIdx.y;
    const int q0 = blockIdx.x * 64;
    const int tid = threadIdx.x;
    const int warp = tid >> 5, lane = tid & 31;
    const int g = lane >> 2, tig = lane & 3;
    const int m0 = warp * 16;
    const int rowL = lane & 15;
    const int colH = (lane >> 4) << 3;
    const float scale = 0.14433756729740643f;

    const __half* base = qkv + (size_t)(b * Nn) * E3 + h * DH;

    // ---- stage Q (raw fp16 copy) + first K/V chunk ----
    for (int i = tid; i < 64 * 6; i += 128) {
        int r = i / 6, c8 = (i % 6) * 8;
        cp_async16(&Qh[r][c8], &base[(size_t)(q0 + r) * E3 + c8]);
        cp_async16(&Ks[0][r][c8], &base[(size_t)r * E3 + Ee + c8]);
        cp_async16(&Vs[0][r][c8], &base[(size_t)r * E3 + 2 * Ee + c8]);
    }
    cp_async_commit();
    cp_async_wait_all();
    __syncthreads();

    // ---- Q fragments (registers, whole kernel) ----
    uint32_t qf[3][4];
#pragma unroll
    for (int kc = 0; kc < 3; ++kc)
        ldm_x4(qf[kc], &Qh[m0 + rowL][16 * kc + colH]);

    float of[6][4];
#pragma unroll
    for (int nb = 0; nb < 6; ++nb)
#pragma unroll
        for (int r = 0; r < 4; ++r) of[nb][r] = 0.0f;
    float mr0 = -1e30f, mr1 = -1e30f, l0 = 0.0f, l1 = 0.0f;

    const int nChunks = Nn / 64;   // 8
    for (int c = 0; c < nChunks; ++c) {
        const int buf = c & 1;
        // prefetch next chunk into other buffer
        if (c + 1 < nChunks) {
            int c0n = (c + 1) * 64;
            for (int i = tid; i < 64 * 6; i += 128) {
                int r = i / 6, c8 = (i % 6) * 8;
                cp_async16(&Ks[buf ^ 1][r][c8],
                           &base[(size_t)(c0n + r) * E3 + Ee + c8]);
                cp_async16(&Vs[buf ^ 1][r][c8],
                           &base[(size_t)(c0n + r) * E3 + 2 * Ee + c8]);
            }
            cp_async_commit();
        }

        // ---- S = Q K^T (ldmatrix B from K rows) ----
        float s[8][4];
#pragma unroll
        for (int jb = 0; jb < 8; ++jb)
#pragma unroll
            for (int r = 0; r < 4; ++r) s[jb][r] = 0.0f;
#pragma unroll
        for (int kc = 0; kc < 3; ++kc) {
#pragma unroll
            for (int jb2 = 0; jb2 < 4; ++jb2) {
                uint32_t t[4];
                ldm_x4(t, &Ks[buf][16 * jb2 + rowL][16 * kc + colH]);
                mma_f16(s[2 * jb2], qf[kc][0], qf[kc][1], qf[kc][2],
                        qf[kc][3], t[0], t[2]);
                mma_f16(s[2 * jb2 + 1], qf[kc][0], qf[kc][1], qf[kc][2],
                        qf[kc][3], t[1], t[3]);
            }
        }

        // ---- scale + online softmax (fp32) ----
        float cm0 = -1e30f, cm1 = -1e30f;
#pragma unroll
        for (int jb = 0; jb < 8; ++jb) {
            s[jb][0] *= scale; s[jb][1] *= scale;
            s[jb][2] *= scale; s[jb][3] *= scale;
            cm0 = fmaxf(cm0, fmaxf(s[jb][0], s[jb][1]));
            cm1 = fmaxf(cm1, fmaxf(s[jb][2], s[jb][3]));
        }
        cm0 = fmaxf(cm0, __shfl_xor_sync(0xffffffffu, cm0, 1));
        cm0 = fmaxf(cm0, __shfl_xor_sync(0xffffffffu, cm0, 2));
        cm1 = fmaxf(cm1, __shfl_xor_sync(0xffffffffu, cm1, 1));
        cm1 = fmaxf(cm1, __shfl_xor_sync(0xffffffffu, cm1, 2));
        float nm0 = fmaxf(mr0, cm0), nm1 = fmaxf(mr1, cm1);
        float corr0 = __expf(mr0 - nm0), corr1 = __expf(mr1 - nm1);
        float rs0 = 0.0f, rs1 = 0.0f;
#pragma unroll
        for (int jb = 0; jb < 8; ++jb) {
            s[jb][0] = __expf(s[jb][0] - nm0);
            s[jb][1] = __expf(s[jb][1] - nm0);
            rs0 += s[jb][0] + s[jb][1];
            s[jb][2] = __expf(s[jb][2] - nm1);
            s[jb][3] = __expf(s[jb][3] - nm1);
            rs1 += s[jb][2] + s[jb][3];
        }
        rs0 += __shfl_xor_sync(0xffffffffu, rs0, 1);
        rs0 += __shfl_xor_sync(0xffffffffu, rs0, 2);
        rs1 += __shfl_xor_sync(0xffffffffu, rs1, 1);
        rs1 += __shfl_xor_sync(0xffffffffu, rs1, 2);
        l0 = l0 * corr0 + rs0;
        l1 = l1 * corr1 + rs1;
        mr0 = nm0; mr1 = nm1;
#pragma unroll
        for (int nb = 0; nb < 6; ++nb) {
            of[nb][0] *= corr0; of[nb][1] *= corr0;
            of[nb][2] *= corr1; of[nb][3] *= corr1;
        }

        // ---- P -> fp16 smem (own warp rows) ----
#pragma unroll
        for (int jb = 0; jb < 8; ++jb) {
            *reinterpret_cast<uint32_t*>(&Ph[m0 + g][8 * jb + 2 * tig]) =
                packh2(s[jb][0], s[jb][1]);
            *reinterpret_cast<uint32_t*>(&Ph[m0 + g + 8][8 * jb + 2 * tig]) =
                packh2(s[jb][2], s[jb][3]);
        }
        __syncwarp();

        // ---- O += P V  (A from Ph, B from V rows via trans ldmatrix) ----
#pragma unroll
        for (int pc = 0; pc < 4; ++pc) {
            uint32_t pa[4];
            ldm_x4(pa, &Ph[m0 + rowL][16 * pc + colH]);
#pragma unroll
            for (int nb2 = 0; nb2 < 3; ++nb2) {
                uint32_t t[4];
                ldm_x4t(t, &Vs[buf][16 * pc + rowL][16 * nb2 + colH]);
                mma_f16(of[2 * nb2], pa[0], pa[1], pa[2], pa[3], t[0], t[1]);
                mma_f16(of[2 * nb2 + 1], pa[0], pa[1], pa[2], pa[3], t[2], t[3]);
            }
        }

        // wait for next chunk + make sure everyone is done with this buffer
        if (c + 1 < nChunks) cp_async_wait_all();
        __syncthreads();
    }

    // ---- epilogue ----
    float inv0 = 1.0f / l0, inv1 = 1.0f / l1;
    float* orow0 = xt + (size_t)(b * Nn + q0 + m0 + g) * Ee + h * DH;
    float* orow1 = orow0 + (size_t)8 * Ee;
#pragma unroll
    for (int nb = 0; nb < 6; ++nb) {
        int col = 8 * nb + 2 * tig;
        *reinterpret_cast<float2*>(&orow0[col]) =
            make_float2(of[nb][0] * inv0, of[nb][1] * inv0);
        *reinterpret_cast<float2*>(&orow1[col]) =
            make_float2(of[nb][2] * inv1, of[nb][3] * inv1);
    }
}

// ---------------------------------------------------------------------------
// Spatial attention: 192 threads, thread = (head, token). (unchanged)
// ---------------------------------------------------------------------------
__global__ __launch_bounds__(192)
void spatial_attn(const float* __restrict__ qkv, float* __restrict__ xs)
{
    __shared__ float sh[8][3 * DH];
    const int gBlk = blockIdx.x;
    const int tid = threadIdx.x;

    const float* base = qkv + (size_t)gBlk * E3;
    for (int j = tid; j < 288; j += 192) {
        int sec = j / 96, w = j - sec * 96;
        int h = w / 12, i4 = w - h * 12;
        float4 v = *reinterpret_cast<const float4*>(
            &base[sec * Ee + h * DH + 4 * i4]);
        *reinterpret_cast<float4*>(&sh[h][sec * DH + 4 * i4]) = v;
    }
    __syncthreads();

    const int h = tid / NT, t = tid - h * NT;
    const float* q = sh[h];
    const float* k = sh[h] + DH;
    const float* v = sh[h] + 2 * DH;
    float q0 = q[t], q1 = q[NT + t];
    float s[NT];
    float mx = -1e30f;
#pragma unroll
    for (int u = 0; u < NT; ++u) {
        s[u] = fmaf(q1, k[NT + u], q0 * k[u]);
        mx = fmaxf(mx, s[u]);
    }
    float sum = 0.0f;
#pragma unroll
    for (int u = 0; u < NT; ++u) { s[u] = __expf(s[u] - mx); sum += s[u]; }
    float inv = 1.0f / sum;
    float o0 = 0.0f, o1 = 0.0f;
#pragma unroll
    for (int u = 0; u < NT; ++u) {
        o0 = fmaf(s[u], v[u], o0);
        o1 = fmaf(s[u], v[NT + u], o1);
    }
    float* op = xs + (size_t)gBlk * Ee + h * DH;
    op[t]      = o0 * inv;
    op[NT + t] = o1 * inv;
}

// ---------------------------------------------------------------------------
// Mean stage 1 + 2 (unchanged)
// ---------------------------------------------------------------------------
__global__ __launch_bounds__(128)
void mean_part(const float* __restrict__ xt, const float* __restrict__ xs,
               float* __restrict__ part)
{
    const int b = blockIdx.x;
    const int j = blockIdx.y * 128 + threadIdx.x;
    const int z = blockIdx.z;
    const float* src = (j < Ee)
        ? xt + (size_t)b * Nn * Ee + (size_t)(z * 128) * Ee + j
        : xs + (size_t)b * Nn * Ee + (size_t)(z * 128) * Ee + (j - Ee);
    float acc = 0.0f;
#pragma unroll 8
    for (int n = 0; n < 128; ++n) acc += src[(size_t)n * Ee];
    part[((size_t)z * Bb + b) * (2 * Ee) + j] = acc;
}

__global__ __launch_bounds__(128)
void mean_reduce(const float* __restrict__ part, float* __restrict__ alphaIn)
{
    const int b = blockIdx.x;
    const int j = blockIdx.y * 128 + threadIdx.x;
    float acc = 0.0f;
#pragma unroll
    for (int z = 0; z < 4; ++z)
        acc += part[((size_t)z * Bb + b) * (2 * Ee) + j];
    alphaIn[b * 2 * Ee + j] = acc * (1.0f / (float)Nn);
}

// ---------------------------------------------------------------------------
// Gating (unchanged)
// ---------------------------------------------------------------------------
__global__ __launch_bounds__(768)
void gate_kernel(const float* __restrict__ alphaIn, const float* __restrict__ Wts,
                 const float* __restrict__ bts,
                 float* __restrict__ g0, float* __restrict__ g1)
{
    __shared__ float a[768];
    __shared__ float val[768];
    const int b = blockIdx.x, t = threadIdx.x;
    a[t] = alphaIn[b * 768 + t];
    __syncthreads();
    float acc = bts[t];
    for (int k = 0; k < 768; ++k)
        acc = fmaf(a[k], Wts[(size_t)k * 768 + t], acc);
    val[t] = acc;
    __syncthreads();
    if (t < Ee) {
        float v0 = val[2 * t], v1 = val[2 * t + 1];
        float mx = fmaxf(v0, v1);
        float e0 = __expf(v0 - mx), e1 = __expf(v1 - mx);
        float inv = 1.0f / (e0 + e1);
        g0[b * Ee + t] = e0 * inv;
        g1[b * Ee + t] = e1 * inv;
    }
}

// ---------------------------------------------------------------------------
// Launch
// ---------------------------------------------------------------------------
extern "C" void kernel_launch(void* const* d_in, const int* in_sizes, int n_in,
                              void* d_out, int out_size)
{
    const float* x      = (const float*)d_in[0];
    const float* Wqkv_t = (const float*)d_in[1];
    const float* bqkv_t = (const float*)d_in[2];
    const float* Wqkv_s = (const float*)d_in[3];
    const float* bqkv_s = (const float*)d_in[4];
    const float* Wts    = (const float*)d_in[5];
    const float* bts    = (const float*)d_in[6];
    const float* Wfc_t  = (const float*)d_in[7];
    const float* bfc_t  = (const float*)d_in[8];
    const float* Wfc_s  = (const float*)d_in[9];
    const float* bfc_s  = (const float*)d_in[10];
    float* out = (float*)d_out;

    float *qkvS, *xt, *xs, *part, *alphaIn, *g0, *g1;
    __half *qkvTh, *xh, *wqT, *wqS, *wfT, *wfS, *xtg, *xsg;
    cudaGetSymbolAddress((void**)&qkvTh,   g_qkvTh);
    cudaGetSymbolAddress((void**)&qkvS,    g_qkv_s);
    cudaGetSymbolAddress((void**)&xt,      g_xt);
    cudaGetSymbolAddress((void**)&xs,      g_xs);
    cudaGetSymbolAddress((void**)&part,    g_alpha_part);
    cudaGetSymbolAddress((void**)&alphaIn, g_alpha_in);
    cudaGetSymbolAddress((void**)&g0,      g_gate0);
    cudaGetSymbolAddress((void**)&g1,      g_gate1);
    cudaGetSymbolAddress((void**)&xh,      g_xh);
    cudaGetSymbolAddress((void**)&wqT,     g_wqT);
    cudaGetSymbolAddress((void**)&wqS,     g_wqS);
    cudaGetSymbolAddress((void**)&wfT,     g_wfT);
    cudaGetSymbolAddress((void**)&wfS,     g_wfS);
    cudaGetSymbolAddress((void**)&xtg,     g_xtg);
    cudaGetSymbolAddress((void**)&xsg,     g_xsg);

    // fp32 -> fp16 conversions
    f2h<<<Mrows * INd / 1024, 256>>>(x, xh);
    f2h<<<INd * E3 / 1024, 256>>>(Wqkv_t, wqT);
    f2h<<<INd * E3 / 1024, 256>>>(Wqkv_s, wqS);
    f2h<<<Ee * OUTd / 1024, 256>>>(Wfc_t, wfT);
    f2h<<<Ee * OUTd / 1024, 256>>>(Wfc_s, wfS);

    // Fused QKV projections (qkvT out in fp16, qkvS in fp32)
    mma_gemm_h<0><<<dim3(18, Mrows / 128), 256, GEMM_SMEM>>>(
        xh, nullptr, wqT, wqS, bqkv_t, bqkv_s, qkvTh, qkvS, nullptr, INd, E3);

    // Attentions
    flash_tattn_h<<<dim3(Nn / 64, Hh, Bb), 128>>>(qkvTh, xt);
    spatial_attn<<<Mrows, 192>>>(qkvS, xs);

    // Gating
    mean_part<<<dim3(Bb, 6, 4), 128>>>(xt, xs, part);
    mean_reduce<<<dim3(Bb, 6), 128>>>(part, alphaIn);
    gate_kernel<<<Bb, 768>>>(alphaIn, Wts, bts, g0, g1);

    // Pre-gated fp16 activations, then fused output projection
    gated_premul_h<<<Mrows * Ee / 1024, 256>>>(xt, xs, g0, g1, xtg, xsg);
    mma_gemm_h<1><<<dim3(OUTd / 128, Mrows / 128), 256, GEMM_SMEM>>>(
        xtg, xsg, wfT, wfS, bfc_t, bfc_s, nullptr, nullptr, out, Ee, OUTd);
}